// round 3
// baseline (speedup 1.0000x reference)
#include <cuda_runtime.h>

// Problem constants: B=1, C=32, S=20, K=5 (125 taps), offset conv out = 375 ch.
#define NV   8000     // 20^3 voxels
#define NC   32       // channels
#define MOUT 375      // 3*K3 offset channels
#define KDIM 4000     // 32 * 125 reduction dim of offset conv

// Scratch (static device globals — no allocation APIs allowed)
__device__ float g_off[MOUT * NV];     // offsets, [o][v]   (12 MB)
__device__ float g_xt[NV * NC];        // x transposed to [v][c] (1 MB)
__device__ float g_attn1[NV * NC];     // deform output, [v][c]
__device__ float g_attn2[NV * NC];     // dilated depthwise output, [v][c]
__device__ float g_wdwt[125 * NC];     // w_dw transposed [t][c]
__device__ float g_wspt[343 * NC];     // w_sp transposed [t][c]

// ---------------------------------------------------------------------------
// Packed fp32x2 helpers (Blackwell FFMA2 — only reachable via PTX)
// ---------------------------------------------------------------------------
__device__ __forceinline__ void fma2(unsigned long long& d,
                                     unsigned long long a,
                                     unsigned long long b) {
    asm("fma.rn.f32x2 %0, %1, %2, %0;" : "+l"(d) : "l"(a), "l"(b));
}
__device__ __forceinline__ unsigned long long pack2(float lo, float hi) {
    unsigned long long r;
    asm("mov.b64 %0, {%1, %2};" : "=l"(r) : "f"(lo), "f"(hi));
    return r;
}
__device__ __forceinline__ void unpack2(float& lo, float& hi, unsigned long long v) {
    asm("mov.b64 {%0, %1}, %2;" : "=f"(lo), "=f"(hi) : "l"(v));
}

// ---------------------------------------------------------------------------
// Prep: transpose x to [v][c], w_dw to [t][c], w_sp to [t][c]
// ---------------------------------------------------------------------------
__global__ __launch_bounds__(256) void prep_kernel(const float* __restrict__ x,
                                                   const float* __restrict__ w_dw,
                                                   const float* __restrict__ w_sp) {
    int idx = blockIdx.x * blockDim.x + threadIdx.x;
    if (idx < NV * NC) {
        int v = idx >> 5, c = idx & 31;
        g_xt[idx] = x[c * NV + v];
    }
    if (idx < 125 * NC) {
        int t = idx >> 5, c = idx & 31;
        g_wdwt[idx] = w_dw[c * 125 + t];
    }
    if (idx < 343 * NC) {
        int t = idx >> 5, c = idx & 31;
        g_wspt[idx] = w_sp[c * 343 + t];
    }
}

// ---------------------------------------------------------------------------
// Stage A: offset conv as implicit GEMM  C[375][8000] = W[375][4000] * Im2col
// 64x64 tile, BK=16, 256 threads, 4x4 microtile, f32x2 packed accumulation.
// ---------------------------------------------------------------------------
__global__ __launch_bounds__(256) void gemm_off_kernel(
    const float* __restrict__ w_off, const float* __restrict__ b_off,
    const float* __restrict__ x) {
    __shared__ __align__(16) float As[16][66];   // [k][m], padded: conflict-free + 8B-aligned pairs
    __shared__ __align__(16) float Bs[16][64];   // [k][n]

    const int tid = threadIdx.x;
    const int n0 = blockIdx.x * 64;
    const int m0 = blockIdx.y * 64;

    // A-load mapping: lanes sweep k (coalesced)
    const int a_lk = tid & 15;
    const int a_lm = tid >> 4;
    // B-load mapping: lanes sweep n (coalesced gather)
    const int b_ln = tid & 63;
    const int b_lr = tid >> 6;
    const int vB = n0 + b_ln;
    const int vz = vB / 400;
    const int vy = (vB / 20) % 20;
    const int vx = vB % 20;
    // compute mapping
    const int tx = tid & 15;
    const int ty = tid >> 4;

    float a_reg[4], b_reg[4];

    auto load_tiles = [&](int k0) {
#pragma unroll
        for (int i = 0; i < 4; i++) {
            int m = m0 + a_lm + 16 * i;
            a_reg[i] = (m < MOUT) ? w_off[m * KDIM + k0 + a_lk] : 0.f;
        }
#pragma unroll
        for (int i = 0; i < 4; i++) {
            int k = k0 + b_lr * 4 + i;
            int c  = k / 125;
            int t  = k - c * 125;
            int kz = t / 25;
            int r  = t - kz * 25;
            int ky = r / 5;
            int kx = r - ky * 5;
            int zi = vz + kz - 2;
            int yi = vy + ky - 2;
            int xi = vx + kx - 2;
            bool ok = ((unsigned)zi < 20u) && ((unsigned)yi < 20u) && ((unsigned)xi < 20u);
            b_reg[i] = ok ? x[c * NV + (zi * 20 + yi) * 20 + xi] : 0.f;
        }
    };

    unsigned long long acc[2][4];
#pragma unroll
    for (int i = 0; i < 2; i++)
#pragma unroll
        for (int j = 0; j < 4; j++) acc[i][j] = 0ull;

    load_tiles(0);
    for (int k0 = 0; k0 < KDIM; k0 += 16) {
        __syncthreads();
#pragma unroll
        for (int i = 0; i < 4; i++) As[a_lk][a_lm + 16 * i] = a_reg[i];
#pragma unroll
        for (int i = 0; i < 4; i++) Bs[b_lr * 4 + i][b_ln] = b_reg[i];
        __syncthreads();
        if (k0 + 16 < KDIM) load_tiles(k0 + 16);   // prefetch next tile (hides LDG latency)

#pragma unroll
        for (int kk = 0; kk < 16; kk++) {
            unsigned long long a0 =
                *reinterpret_cast<const unsigned long long*>(&As[kk][ty * 4]);
            unsigned long long a1 =
                *reinterpret_cast<const unsigned long long*>(&As[kk][ty * 4 + 2]);
            float4 b4 = *reinterpret_cast<const float4*>(&Bs[kk][tx * 4]);
            unsigned long long b0 = pack2(b4.x, b4.x);
            unsigned long long b1 = pack2(b4.y, b4.y);
            unsigned long long b2 = pack2(b4.z, b4.z);
            unsigned long long b3 = pack2(b4.w, b4.w);
            fma2(acc[0][0], a0, b0); fma2(acc[1][0], a1, b0);
            fma2(acc[0][1], a0, b1); fma2(acc[1][1], a1, b1);
            fma2(acc[0][2], a0, b2); fma2(acc[1][2], a1, b2);
            fma2(acc[0][3], a0, b3); fma2(acc[1][3], a1, b3);
        }
    }

    // Epilogue: acc[ip][j] holds (m = ty*4+2*ip, ty*4+2*ip+1) x (n = tx*4+j)
#pragma unroll
    for (int ip = 0; ip < 2; ip++) {
#pragma unroll
        for (int j = 0; j < 4; j++) {
            float lo, hi;
            unpack2(lo, hi, acc[ip][j]);
            int m_lo = m0 + ty * 4 + 2 * ip;
            int n = n0 + tx * 4 + j;
            if (m_lo < MOUT)     g_off[m_lo * NV + n]       = lo + b_off[m_lo];
            if (m_lo + 1 < MOUT) g_off[(m_lo + 1) * NV + n] = hi + b_off[m_lo + 1];
        }
    }
}

// ---------------------------------------------------------------------------
// Stage B: deformable depthwise conv. One warp per voxel, lane = channel.
// All 8 trilinear corner gathers are single coalesced 128B lines ([v][c] layout).
// ---------------------------------------------------------------------------
__global__ __launch_bounds__(256) void deform_kernel(const float* __restrict__ b_dw) {
    const int lane = threadIdx.x & 31;
    const int v = blockIdx.x * 8 + (threadIdx.x >> 5);
    const int vz = v / 400;
    const int vy = (v / 20) % 20;
    const int vx = v % 20;

    float acc = 0.f;
#pragma unroll 1
    for (int kz = 0; kz < 5; kz++) {
#pragma unroll 1
        for (int ky = 0; ky < 5; ky++) {
#pragma unroll
            for (int kx = 0; kx < 5; kx++) {
                int t = (kz * 5 + ky) * 5 + kx;
                // offsets: same address for all lanes (broadcast)
                float oz = g_off[(t * 3 + 0) * NV + v];
                float oy = g_off[(t * 3 + 1) * NV + v];
                float ox = g_off[(t * 3 + 2) * NV + v];
                float pd = (float)(vz + kz - 2) + oz;
                float ph = (float)(vy + ky - 2) + oy;
                float pw = (float)(vx + kx - 2) + ox;
                float d0f = floorf(pd), h0f = floorf(ph), w0f = floorf(pw);
                float fd = pd - d0f, fh = ph - h0f, fw = pw - w0f;
                int d0 = (int)d0f, h0 = (int)h0f, w0 = (int)w0f;
                // per-dim weights with validity folded in (valid = product over dims)
                float wz0 = ((unsigned)d0       < 20u) ? (1.f - fd) : 0.f;
                float wz1 = ((unsigned)(d0 + 1) < 20u) ? fd         : 0.f;
                float wy0 = ((unsigned)h0       < 20u) ? (1.f - fh) : 0.f;
                float wy1 = ((unsigned)(h0 + 1) < 20u) ? fh         : 0.f;
                float wx0 = ((unsigned)w0       < 20u) ? (1.f - fw) : 0.f;
                float wx1 = ((unsigned)(w0 + 1) < 20u) ? fw         : 0.f;
                int iz0 = min(max(d0, 0), 19),     iz1 = min(max(d0 + 1, 0), 19);
                int iy0 = min(max(h0, 0), 19),     iy1 = min(max(h0 + 1, 0), 19);
                int ix0 = min(max(w0, 0), 19),     ix1 = min(max(w0 + 1, 0), 19);
                int r00 = (iz0 * 20 + iy0) * 20;
                int r01 = (iz0 * 20 + iy1) * 20;
                int r10 = (iz1 * 20 + iy0) * 20;
                int r11 = (iz1 * 20 + iy1) * 20;
                float x000 = g_xt[(r00 + ix0) * 32 + lane];
                float x001 = g_xt[(r00 + ix1) * 32 + lane];
                float x010 = g_xt[(r01 + ix0) * 32 + lane];
                float x011 = g_xt[(r01 + ix1) * 32 + lane];
                float x100 = g_xt[(r10 + ix0) * 32 + lane];
                float x101 = g_xt[(r10 + ix1) * 32 + lane];
                float x110 = g_xt[(r11 + ix0) * 32 + lane];
                float x111 = g_xt[(r11 + ix1) * 32 + lane];
                float s = wz0 * (wy0 * (wx0 * x000 + wx1 * x001) +
                                 wy1 * (wx0 * x010 + wx1 * x011)) +
                          wz1 * (wy0 * (wx0 * x100 + wx1 * x101) +
                                 wy1 * (wx0 * x110 + wx1 * x111));
                acc += g_wdwt[t * 32 + lane] * s;
            }
        }
    }
    g_attn1[v * 32 + lane] = acc + b_dw[lane];
}

// ---------------------------------------------------------------------------
// Stage C: dilated (3) 7x7x7 depthwise conv, pad 9. Warp per voxel, lane = ch.
// ---------------------------------------------------------------------------
__global__ __launch_bounds__(256) void spconv_kernel(const float* __restrict__ b_sp) {
    const int lane = threadIdx.x & 31;
    const int v = blockIdx.x * 8 + (threadIdx.x >> 5);
    const int vz = v / 400;
    const int vy = (v / 20) % 20;
    const int vx = v % 20;

    float acc = b_sp[lane];
#pragma unroll 1
    for (int kz = 0; kz < 7; kz++) {
        int zi = vz + kz * 3 - 9;
        if ((unsigned)zi >= 20u) continue;
#pragma unroll 1
        for (int ky = 0; ky < 7; ky++) {
            int yi = vy + ky * 3 - 9;
            if ((unsigned)yi >= 20u) continue;
            int rowbase = (zi * 20 + yi) * 20;
            int tbase = (kz * 7 + ky) * 7;
#pragma unroll
            for (int kx = 0; kx < 7; kx++) {
                int xi = vx + kx * 3 - 9;
                if ((unsigned)xi < 20u)
                    acc += g_wspt[(tbase + kx) * 32 + lane] *
                           g_attn1[(rowbase + xi) * 32 + lane];
            }
        }
    }
    g_attn2[v * 32 + lane] = acc;
}

// ---------------------------------------------------------------------------
// Stage D: 32x32 pointwise (+bias) fused with final x*attn, NCDHW output.
// Block handles 32 voxels x 32 out-channels via smem tiles.
// ---------------------------------------------------------------------------
__global__ __launch_bounds__(256) void pw_kernel(const float* __restrict__ w_pw,
                                                 const float* __restrict__ b_pw,
                                                 const float* __restrict__ x,
                                                 float* __restrict__ out) {
    __shared__ float a_s[32][33];   // [voxel][channel], padded for conflict-free column reads
    __shared__ float w_s[1024];     // w_pw[o][c]
    const int tid = threadIdx.x;
    const int v0 = blockIdx.x * 32;
#pragma unroll
    for (int i = 0; i < 4; i++) {
        int e = tid + 256 * i;
        w_s[e] = w_pw[e];
        int vv = e >> 5, cc = e & 31;
        a_s[vv][cc] = g_attn2[v0 * 32 + e];
    }
    __syncthreads();

    const int lane = tid & 31;   // voxel within tile
    const int wq = tid >> 5;     // 0..7
#pragma unroll
    for (int i = 0; i < 4; i++) {
        int o = wq + 8 * i;      // out channel (same across warp -> broadcast w reads)
        float acc = b_pw[o];
#pragma unroll
        for (int c = 0; c < 32; c++)
            acc += w_s[o * 32 + c] * a_s[lane][c];
        int v = v0 + lane;
        out[o * NV + v] = x[o * NV + v] * acc;   // coalesced
    }
}

// ---------------------------------------------------------------------------
extern "C" void kernel_launch(void* const* d_in, const int* in_sizes, int n_in,
                              void* d_out, int out_size) {
    const float* x     = (const float*)d_in[0];
    const float* w_off = (const float*)d_in[1];
    const float* b_off = (const float*)d_in[2];
    const float* w_dw  = (const float*)d_in[3];
    const float* b_dw  = (const float*)d_in[4];
    const float* w_sp  = (const float*)d_in[5];
    const float* b_sp  = (const float*)d_in[6];
    const float* w_pw  = (const float*)d_in[7];
    const float* b_pw  = (const float*)d_in[8];
    float* out = (float*)d_out;

    prep_kernel<<<1000, 256>>>(x, w_dw, w_sp);
    dim3 gg(125, 6);                       // 8000/64 n-tiles x ceil(375/64) m-tiles
    gemm_off_kernel<<<gg, 256>>>(w_off, b_off, x);
    deform_kernel<<<1000, 256>>>(b_dw);
    spconv_kernel<<<1000, 256>>>(b_sp);
    pw_kernel<<<250, 256>>>(w_pw, b_pw, x, out);
}

// round 7
// speedup vs baseline: 2.1498x; 2.1498x over previous
#include <cuda_runtime.h>
#include <cuda_bf16.h>
#include <cstdint>

// Problem constants: B=1, C=32, S=20, K=5 (125 taps), offset conv out = 375 ch.
#define NV   8000     // 20^3 voxels
#define NC   32       // channels
#define MOUT 375      // 3*K3 offset channels
#define MPAD 384      // padded to 2 x 192 n-tiles

// Scratch (static device globals — no allocation APIs allowed)
__device__ float g_off[MOUT * NV];     // offsets, [o][v]
__device__ float g_xt[NV * NC];        // x transposed to [v][c]
__device__ float g_attn1[NV * NC];     // deform output, [v][c]
__device__ float g_attn2[NV * NC];     // dilated depthwise output, [v][c]
__device__ float g_wdwt[125 * NC];     // w_dw transposed [t][c]
__device__ float g_wspt[343 * NC];     // w_sp transposed [t][c]
// bf16-split operands for the HMMA offset GEMM
__device__ __align__(16) __nv_bfloat16 g_A[125 * MPAD * 64];  // per tap: [m][hi c0..31 | lo c0..31]
__device__ __align__(16) __nv_bfloat16 g_xpair[NV * 64];      // per voxel: [hi c0..31 | lo c0..31]

__device__ __forceinline__ uint32_t smem_u32(const void* p) {
    uint32_t a;
    asm("{ .reg .u64 t; cvta.to.shared.u64 t, %1; cvt.u32.u64 %0, t; }" : "=r"(a) : "l"(p));
    return a;
}
__device__ __forceinline__ uint32_t sw128(uint32_t off) { return off ^ ((off >> 3) & 0x70); }

// cp.async 16B with zero-fill predication (src-size = 0 skips the read)
__device__ __forceinline__ void cp16(uint32_t dst, const void* src, bool pred) {
    int sz = pred ? 16 : 0;
    asm volatile("cp.async.cg.shared.global [%0], [%1], 16, %2;" :: "r"(dst), "l"(src), "r"(sz));
}
#define CP_COMMIT() asm volatile("cp.async.commit_group;" ::: "memory")
#define CP_WAIT(N)  asm volatile("cp.async.wait_group %0;" :: "n"(N) : "memory")

__device__ __forceinline__ void ldsm_x4(uint32_t& r0, uint32_t& r1, uint32_t& r2,
                                        uint32_t& r3, uint32_t addr) {
    asm volatile("ldmatrix.sync.aligned.m8n8.x4.shared.b16 {%0,%1,%2,%3}, [%4];"
                 : "=r"(r0), "=r"(r1), "=r"(r2), "=r"(r3) : "r"(addr));
}
// B operand: W stored k-contiguous ([o][k]) -> NON-trans gives the row.col B fragment
__device__ __forceinline__ void ldsm_x2(uint32_t& r0, uint32_t& r1, uint32_t addr) {
    asm volatile("ldmatrix.sync.aligned.m8n8.x2.shared.b16 {%0,%1}, [%2];"
                 : "=r"(r0), "=r"(r1) : "r"(addr));
}
__device__ __forceinline__ void mma16816(float* c, const uint32_t* a, const uint32_t* b) {
    asm volatile("mma.sync.aligned.m16n8k16.row.col.f32.bf16.bf16.f32 "
                 "{%0,%1,%2,%3}, {%4,%5,%6,%7}, {%8,%9}, {%0,%1,%2,%3};"
                 : "+f"(c[0]), "+f"(c[1]), "+f"(c[2]), "+f"(c[3])
                 : "r"(a[0]), "r"(a[1]), "r"(a[2]), "r"(a[3]), "r"(b[0]), "r"(b[1]));
}

// ---------------------------------------------------------------------------
// Prep: transposes + bf16 hi/lo split of x ([v][hi c|lo c])
// ---------------------------------------------------------------------------
__global__ __launch_bounds__(256) void prep_kernel(const float* __restrict__ x,
                                                   const float* __restrict__ w_dw,
                                                   const float* __restrict__ w_sp) {
    int idx = blockIdx.x * blockDim.x + threadIdx.x;
    if (idx < NV * 64) {  // g_xpair
        int v = idx >> 6, j = idx & 63, c = j & 31;
        float val = x[c * NV + v];
        __nv_bfloat16 hi = __float2bfloat16(val);
        g_xpair[idx] = (j < 32) ? hi : __float2bfloat16(val - __bfloat162float(hi));
    }
    if (idx < NV * NC) {
        int v = idx >> 5, c = idx & 31;
        g_xt[idx] = x[c * NV + v];
    }
    if (idx < 125 * NC) {
        int t = idx >> 5, c = idx & 31;
        g_wdwt[idx] = w_dw[c * 125 + t];
    }
    if (idx < 343 * NC) {
        int t = idx >> 5, c = idx & 31;
        g_wspt[idx] = w_sp[c * 343 + t];
    }
}

// Prep A: per tap t, rows m 0..383: [hi(w[m][c][t]) c0..31 | lo c0..31]
__global__ __launch_bounds__(256) void prep_a_kernel(const float* __restrict__ w_off) {
    int idx = blockIdx.x * blockDim.x + threadIdx.x;   // 125*384*64
    int t = idx / (MPAD * 64);
    int r = idx - t * (MPAD * 64);
    int m = r >> 6, j = r & 63, c = j & 31;
    float w = (m < MOUT) ? w_off[m * 4000 + c * 125 + t] : 0.f;
    __nv_bfloat16 hi = __float2bfloat16(w);
    g_A[idx] = (j < 32) ? hi : __float2bfloat16(w - __bfloat162float(hi));
}

// ---------------------------------------------------------------------------
// Stage A: offset conv as 125 tap-GEMMs via mma.sync bf16.
// C[v=8000][o=384] tiles: CTA = 128 voxels x 192 out-ch, 8 warps (2m x 4n),
// warp tile 64v x 48o -> 4x6 m16n8 frags. Per tap: K_eff = 96 via bf16 split
// segments (Xh,Wh),(Xl,Wh),(Xh,Wl). cp.async double-buffered fills.
// ---------------------------------------------------------------------------
#define WS0 0
#define WS1 24576
#define XS0 49152
#define XS1 65536
#define SMEM_SZ 81920

__global__ __launch_bounds__(256, 1) void gemm_off_kernel(const float* __restrict__ b_off) {
    extern __shared__ __align__(1024) char smem[];
    const uint32_t sb = smem_u32(smem);
    const int tid = threadIdx.x;
    const int lane = tid & 31;
    const int w = tid >> 5;
    const int wm = w & 1;          // m half (64 voxels)
    const int wn = w >> 1;         // n quarter (48 ch)
    const int v0 = blockIdx.x * 128;
    const int n0c = blockIdx.y * 192;

    const uint32_t wbase[2] = {sb + WS0, sb + WS1};
    const uint32_t xbase[2] = {sb + XS0, sb + XS1};

    // X fill mapping: 2 threads per voxel row
    const int bn = tid >> 1;             // row 0..127
    const int bh = (tid & 1) * 4;        // 16B-chunk base
    const int vq = v0 + bn;
    const bool vok = vq < NV;
    const int vz = vq / 400, vy = (vq / 20) % 20, vx = vq % 20;
    const char* __restrict__ xpB = (const char*)g_xpair;
    const char* __restrict__ gAB = (const char*)g_A;

    auto load_tap = [&](int t, int s) {
        // W tile: 192 rows x 128B from g_A[t][n0c + row]
        const char* wsrc = gAB + (size_t)(t * MPAD + n0c) * 128;
#pragma unroll
        for (int i = 0; i < 6; i++) {
            int chunk = tid + (i << 8);            // 0..1535
            int row = chunk >> 3, cb = (chunk & 7) << 4;
            cp16(wbase[s] + sw128((row << 7) + cb), wsrc + (row << 7) + cb, true);
        }
        // X tile: 128 rows x 128B from g_xpair[shifted voxel]
        const int dz = t / 25 - 2, dy = (t / 5) % 5 - 2, dx = t % 5 - 2;
        const bool valid = vok && ((unsigned)(vz + dz) < 20u) &&
                           ((unsigned)(vy + dy) < 20u) && ((unsigned)(vx + dx) < 20u);
        const int vsrc = valid ? (vq + dz * 400 + dy * 20 + dx) : 0;
        const char* xsrc = xpB + (size_t)vsrc * 128;
#pragma unroll
        for (int i = 0; i < 4; i++) {
            int cb = (bh + i) << 4;
            cp16(xbase[s] + sw128((bn << 7) + cb), xsrc + cb, valid);
        }
    };

    float acc[4][6][4];
#pragma unroll
    for (int mf = 0; mf < 4; mf++)
#pragma unroll
        for (int nf = 0; nf < 6; nf++)
#pragma unroll
            for (int q = 0; q < 4; q++) acc[mf][nf][q] = 0.f;

    // ldmatrix per-thread address components
    const int x_row = wm * 64 + (lane & 15);      // + mf*16
    const int x_hi16 = (lane >> 4) << 4;          // 16B half select
    const int w_row = wn * 48 + (lane & 7);       // + nf*8
    const int w_hi16 = ((lane >> 3) & 1) << 4;    // k-half select (x2: lanes 0-15)

    // segment k-offsets (bytes): X: hi=0/32, lo=64/96 ; W likewise
    const int xseg[6] = {0, 32, 64, 96, 0, 32};
    const int wseg[6] = {0, 32, 0, 32, 64, 96};

    load_tap(0, 0);
    CP_COMMIT();

    for (int t = 0; t < 125; t++) {
        const int s = t & 1;
        if (t < 124) { load_tap(t + 1, s ^ 1); CP_COMMIT(); CP_WAIT(1); }
        else         { CP_WAIT(0); }
        __syncthreads();

        const uint32_t xb = xbase[s];
        const uint32_t wb = wbase[s];
#pragma unroll
        for (int seg = 0; seg < 6; seg++) {
            uint32_t af[4][4];
#pragma unroll
            for (int mf = 0; mf < 4; mf++)
                ldsm_x4(af[mf][0], af[mf][1], af[mf][2], af[mf][3],
                        xb + sw128(((x_row + mf * 16) << 7) + xseg[seg] + x_hi16));
            uint32_t bf[6][2];
#pragma unroll
            for (int nf = 0; nf < 6; nf++)
                ldsm_x2(bf[nf][0], bf[nf][1],
                        wb + sw128(((w_row + nf * 8) << 7) + wseg[seg] + w_hi16));
#pragma unroll
            for (int mf = 0; mf < 4; mf++)
#pragma unroll
                for (int nf = 0; nf < 6; nf++)
                    mma16816(acc[mf][nf], af[mf], bf[nf]);
        }
        __syncthreads();
    }

    // Epilogue: frag (mf,nf): c0 at (v = v0+wm*64+mf*16+lane/4,      o = n0c+wn*48+nf*8+(lane%4)*2)
    //                         c1 (v, o+1)   c2 (v+8, o)   c3 (v+8, o+1)
    const int vr = v0 + wm * 64 + (lane >> 2);
    const int ob = n0c + wn * 48 + (lane & 3) * 2;
#pragma unroll
    for (int nf = 0; nf < 6; nf++) {
        int o = ob + nf * 8;
        float bias0 = (o < MOUT) ? b_off[o] : 0.f;
        float bias1 = (o + 1 < MOUT) ? b_off[o + 1] : 0.f;
#pragma unroll
        for (int mf = 0; mf < 4; mf++) {
            int v1 = vr + mf * 16, v2 = v1 + 8;
            if (o < MOUT) {
                if (v1 < NV) g_off[o * NV + v1] = acc[mf][nf][0] + bias0;
                if (v2 < NV) g_off[o * NV + v2] = acc[mf][nf][2] + bias0;
            }
            if (o + 1 < MOUT) {
                if (v1 < NV) g_off[(o + 1) * NV + v1] = acc[mf][nf][1] + bias1;
                if (v2 < NV) g_off[(o + 1) * NV + v2] = acc[mf][nf][3] + bias1;
            }
        }
    }
}

// ---------------------------------------------------------------------------
// Stage B: deformable depthwise conv. One warp per voxel, lane = channel.
// ---------------------------------------------------------------------------
__global__ __launch_bounds__(256) void deform_kernel(const float* __restrict__ b_dw) {
    const int lane = threadIdx.x & 31;
    const int v = blockIdx.x * 8 + (threadIdx.x >> 5);
    const int vz = v / 400;
    const int vy = (v / 20) % 20;
    const int vx = v % 20;

    float acc = 0.f;
#pragma unroll 1
    for (int kz = 0; kz < 5; kz++) {
#pragma unroll 1
        for (int ky = 0; ky < 5; ky++) {
#pragma unroll
            for (int kx = 0; kx < 5; kx++) {
                int t = (kz * 5 + ky) * 5 + kx;
                float oz = g_off[(t * 3 + 0) * NV + v];
                float oy = g_off[(t * 3 + 1) * NV + v];
                float ox = g_off[(t * 3 + 2) * NV + v];
                float pd = (float)(vz + kz - 2) + oz;
                float ph = (float)(vy + ky - 2) + oy;
                float pw = (float)(vx + kx - 2) + ox;
                float d0f = floorf(pd), h0f = floorf(ph), w0f = floorf(pw);
                float fd = pd - d0f, fh = ph - h0f, fw = pw - w0f;
                int d0 = (int)d0f, h0 = (int)h0f, w0 = (int)w0f;
                float wz0 = ((unsigned)d0       < 20u) ? (1.f - fd) : 0.f;
                float wz1 = ((unsigned)(d0 + 1) < 20u) ? fd         : 0.f;
                float wy0 = ((unsigned)h0       < 20u) ? (1.f - fh) : 0.f;
                float wy1 = ((unsigned)(h0 + 1) < 20u) ? fh         : 0.f;
                float wx0 = ((unsigned)w0       < 20u) ? (1.f - fw) : 0.f;
                float wx1 = ((unsigned)(w0 + 1) < 20u) ? fw         : 0.f;
                int iz0 = min(max(d0, 0), 19),     iz1 = min(max(d0 + 1, 0), 19);
                int iy0 = min(max(h0, 0), 19),     iy1 = min(max(h0 + 1, 0), 19);
                int ix0 = min(max(w0, 0), 19),     ix1 = min(max(w0 + 1, 0), 19);
                int r00 = (iz0 * 20 + iy0) * 20;
                int r01 = (iz0 * 20 + iy1) * 20;
                int r10 = (iz1 * 20 + iy0) * 20;
                int r11 = (iz1 * 20 + iy1) * 20;
                float x000 = g_xt[(r00 + ix0) * 32 + lane];
                float x001 = g_xt[(r00 + ix1) * 32 + lane];
                float x010 = g_xt[(r01 + ix0) * 32 + lane];
                float x011 = g_xt[(r01 + ix1) * 32 + lane];
                float x100 = g_xt[(r10 + ix0) * 32 + lane];
                float x101 = g_xt[(r10 + ix1) * 32 + lane];
                float x110 = g_xt[(r11 + ix0) * 32 + lane];
                float x111 = g_xt[(r11 + ix1) * 32 + lane];
                float s = wz0 * (wy0 * (wx0 * x000 + wx1 * x001) +
                                 wy1 * (wx0 * x010 + wx1 * x011)) +
                          wz1 * (wy0 * (wx0 * x100 + wx1 * x101) +
                                 wy1 * (wx0 * x110 + wx1 * x111));
                acc += g_wdwt[t * 32 + lane] * s;
            }
        }
    }
    g_attn1[v * 32 + lane] = acc + b_dw[lane];
}

// ---------------------------------------------------------------------------
// Stage C: dilated (3) 7x7x7 depthwise conv, pad 9. Warp per voxel, lane = ch.
// ---------------------------------------------------------------------------
__global__ __launch_bounds__(256) void spconv_kernel(const float* __restrict__ b_sp) {
    const int lane = threadIdx.x & 31;
    const int v = blockIdx.x * 8 + (threadIdx.x >> 5);
    const int vz = v / 400;
    const int vy = (v / 20) % 20;
    const int vx = v % 20;

    float acc = b_sp[lane];
#pragma unroll 1
    for (int kz = 0; kz < 7; kz++) {
        int zi = vz + kz * 3 - 9;
        if ((unsigned)zi >= 20u) continue;
#pragma unroll 1
        for (int ky = 0; ky < 7; ky++) {
            int yi = vy + ky * 3 - 9;
            if ((unsigned)yi >= 20u) continue;
            int rowbase = (zi * 20 + yi) * 20;
            int tbase = (kz * 7 + ky) * 7;
#pragma unroll
            for (int kx = 0; kx < 7; kx++) {
                int xi = vx + kx * 3 - 9;
                if ((unsigned)xi < 20u)
                    acc += g_wspt[(tbase + kx) * 32 + lane] *
                           g_attn1[(rowbase + xi) * 32 + lane];
            }
        }
    }
    g_attn2[v * 32 + lane] = acc;
}

// ---------------------------------------------------------------------------
// Stage D: 32x32 pointwise (+bias) fused with final x*attn, NCDHW output.
// ---------------------------------------------------------------------------
__global__ __launch_bounds__(256) void pw_kernel(const float* __restrict__ w_pw,
                                                 const float* __restrict__ b_pw,
                                                 const float* __restrict__ x,
                                                 float* __restrict__ out) {
    __shared__ float a_s[32][33];
    __shared__ float w_s[1024];
    const int tid = threadIdx.x;
    const int v0 = blockIdx.x * 32;
#pragma unroll
    for (int i = 0; i < 4; i++) {
        int e = tid + 256 * i;
        w_s[e] = w_pw[e];
        int vv = e >> 5, cc = e & 31;
        a_s[vv][cc] = g_attn2[v0 * 32 + e];
    }
    __syncthreads();

    const int lane = tid & 31;
    const int wq = tid >> 5;
#pragma unroll
    for (int i = 0; i < 4; i++) {
        int o = wq + 8 * i;
        float acc = b_pw[o];
#pragma unroll
        for (int c = 0; c < 32; c++)
            acc += w_s[o * 32 + c] * a_s[lane][c];
        int v = v0 + lane;
        out[o * NV + v] = x[o * NV + v] * acc;
    }
}

// ---------------------------------------------------------------------------
extern "C" void kernel_launch(void* const* d_in, const int* in_sizes, int n_in,
                              void* d_out, int out_size) {
    const float* x     = (const float*)d_in[0];
    const float* w_off = (const float*)d_in[1];
    const float* b_off = (const float*)d_in[2];
    const float* w_dw  = (const float*)d_in[3];
    const float* b_dw  = (const float*)d_in[4];
    const float* w_sp  = (const float*)d_in[5];
    const float* b_sp  = (const float*)d_in[6];
    const float* w_pw  = (const float*)d_in[7];
    const float* b_pw  = (const float*)d_in[8];
    float* out = (float*)d_out;

    cudaFuncSetAttribute(gemm_off_kernel,
                         cudaFuncAttributeMaxDynamicSharedMemorySize, SMEM_SZ);

    prep_kernel<<<2000, 256>>>(x, w_dw, w_sp);
    prep_a_kernel<<<12000, 256>>>(w_off);              // 125*384*64 / 256
    dim3 gg(63, 2);                                    // 63 v-tiles x 2 n-tiles
    gemm_off_kernel<<<gg, 256, SMEM_SZ>>>(b_off);
    deform_kernel<<<1000, 256>>>(b_dw);
    spconv_kernel<<<1000, 256>>>(b_sp);
    pw_kernel<<<250, 256>>>(w_pw, b_pw, x, out);
}

// round 8
// speedup vs baseline: 2.4790x; 1.1531x over previous
#include <cuda_runtime.h>
#include <cuda_bf16.h>
#include <cstdint>

// Problem constants: B=1, C=32, S=20, K=5 (125 taps), offset conv out = 375 ch.
#define NV   8000     // 20^3 voxels
#define NC   32       // channels
#define MOUT 375      // 3*K3 offset channels
#define MPAD 384      // padded to 2 x 192 n-tiles

// Scratch (static device globals — no allocation APIs allowed)
__device__ float g_off[MOUT * NV];     // offsets, [o][v]
__device__ float g_xt[NV * NC];        // x transposed to [v][c]
__device__ float g_attn1[NV * NC];     // deform output, [v][c]
__device__ float g_attn2[NV * NC];     // dilated depthwise output, [v][c]
__device__ float g_wdwt[125 * NC];     // w_dw transposed [t][c]
__device__ float g_wspt[343 * NC];     // w_sp transposed [t][c]
// bf16-split operands for the HMMA offset GEMM
__device__ __align__(16) __nv_bfloat16 g_A[125 * MPAD * 64];  // per tap: [m][hi c0..31 | lo c0..31]
__device__ __align__(16) __nv_bfloat16 g_xpair[NV * 64];      // per voxel: [hi c0..31 | lo c0..31]

__device__ __forceinline__ uint32_t smem_u32(const void* p) {
    uint32_t a;
    asm("{ .reg .u64 t; cvta.to.shared.u64 t, %1; cvt.u32.u64 %0, t; }" : "=r"(a) : "l"(p));
    return a;
}
__device__ __forceinline__ uint32_t sw128(uint32_t off) { return off ^ ((off >> 3) & 0x70); }

// cp.async 16B with zero-fill predication (src-size = 0 skips the read)
__device__ __forceinline__ void cp16(uint32_t dst, const void* src, bool pred) {
    int sz = pred ? 16 : 0;
    asm volatile("cp.async.cg.shared.global [%0], [%1], 16, %2;" :: "r"(dst), "l"(src), "r"(sz));
}
#define CP_COMMIT() asm volatile("cp.async.commit_group;" ::: "memory")
#define CP_WAIT(N)  asm volatile("cp.async.wait_group %0;" :: "n"(N) : "memory")

__device__ __forceinline__ void ldsm_x4(uint32_t& r0, uint32_t& r1, uint32_t& r2,
                                        uint32_t& r3, uint32_t addr) {
    asm volatile("ldmatrix.sync.aligned.m8n8.x4.shared.b16 {%0,%1,%2,%3}, [%4];"
                 : "=r"(r0), "=r"(r1), "=r"(r2), "=r"(r3) : "r"(addr));
}
// B operand: W stored k-contiguous ([o][k]) -> NON-trans gives the row.col B fragment
__device__ __forceinline__ void ldsm_x2(uint32_t& r0, uint32_t& r1, uint32_t addr) {
    asm volatile("ldmatrix.sync.aligned.m8n8.x2.shared.b16 {%0,%1}, [%2];"
                 : "=r"(r0), "=r"(r1) : "r"(addr));
}
__device__ __forceinline__ void mma16816(float* c, const uint32_t* a, const uint32_t* b) {
    asm volatile("mma.sync.aligned.m16n8k16.row.col.f32.bf16.bf16.f32 "
                 "{%0,%1,%2,%3}, {%4,%5,%6,%7}, {%8,%9}, {%0,%1,%2,%3};"
                 : "+f"(c[0]), "+f"(c[1]), "+f"(c[2]), "+f"(c[3])
                 : "r"(a[0]), "r"(a[1]), "r"(a[2]), "r"(a[3]), "r"(b[0]), "r"(b[1]));
}

// ---------------------------------------------------------------------------
// Prep: transposes + bf16 hi/lo split of x ([v][hi c|lo c])
// ---------------------------------------------------------------------------
__global__ __launch_bounds__(256) void prep_kernel(const float* __restrict__ x,
                                                   const float* __restrict__ w_dw,
                                                   const float* __restrict__ w_sp) {
    int idx = blockIdx.x * blockDim.x + threadIdx.x;
    if (idx < NV * 64) {  // g_xpair
        int v = idx >> 6, j = idx & 63, c = j & 31;
        float val = x[c * NV + v];
        __nv_bfloat16 hi = __float2bfloat16(val);
        g_xpair[idx] = (j < 32) ? hi : __float2bfloat16(val - __bfloat162float(hi));
    }
    if (idx < NV * NC) {
        int v = idx >> 5, c = idx & 31;
        g_xt[idx] = x[c * NV + v];
    }
    if (idx < 125 * NC) {
        int t = idx >> 5, c = idx & 31;
        g_wdwt[idx] = w_dw[c * 125 + t];
    }
    if (idx < 343 * NC) {
        int t = idx >> 5, c = idx & 31;
        g_wspt[idx] = w_sp[c * 343 + t];
    }
}

// Prep A (coalesced): one block per output row m. w_off row m = 4000 contiguous
// floats -> coalesced load to smem; scatter bf16 hi/lo pairs per tap.
// smem read stride 125 is conflict-free (gcd(125,32)=1).
__global__ __launch_bounds__(256) void prep_a_kernel(const float* __restrict__ w_off) {
    __shared__ float row[4000];
    const int m = blockIdx.x;
    const int tid = threadIdx.x;
    const bool mok = m < MOUT;
    if (mok)
        for (int i = tid; i < 4000; i += 256) row[i] = w_off[m * 4000 + i];
    __syncthreads();
    const int lane = tid & 31;
    const int wq = tid >> 5;
    for (int t = wq; t < 125; t += 8) {
        float wv = mok ? row[lane * 125 + t] : 0.f;
        __nv_bfloat16 hi = __float2bfloat16(wv);
        __nv_bfloat16 lo = __float2bfloat16(wv - __bfloat162float(hi));
        size_t base = ((size_t)t * MPAD + m) * 64;
        g_A[base + lane] = hi;
        g_A[base + 32 + lane] = lo;
    }
}

// ---------------------------------------------------------------------------
// Stage A: offset conv as 125 tap-GEMMs via mma.sync bf16.
// C[v=8000][o=384] tiles: CTA = 128 voxels x 192 out-ch, 8 warps (2m x 4n),
// warp tile 64v x 48o -> 4x6 m16n8 frags. Per tap: K_eff = 96 via bf16 split
// segments (Xh,Wh),(Xl,Wh),(Xh,Wl). cp.async double-buffered fills.
// ---------------------------------------------------------------------------
#define WS0 0
#define WS1 24576
#define XS0 49152
#define XS1 65536
#define SMEM_SZ 81920

__global__ __launch_bounds__(256, 1) void gemm_off_kernel(const float* __restrict__ b_off) {
    extern __shared__ __align__(1024) char smem[];
    const uint32_t sb = smem_u32(smem);
    const int tid = threadIdx.x;
    const int lane = tid & 31;
    const int w = tid >> 5;
    const int wm = w & 1;          // m half (64 voxels)
    const int wn = w >> 1;         // n quarter (48 ch)
    const int v0 = blockIdx.x * 128;
    const int n0c = blockIdx.y * 192;

    const uint32_t wbase[2] = {sb + WS0, sb + WS1};
    const uint32_t xbase[2] = {sb + XS0, sb + XS1};

    // X fill mapping: 2 threads per voxel row
    const int bn = tid >> 1;             // row 0..127
    const int bh = (tid & 1) * 4;        // 16B-chunk base
    const int vq = v0 + bn;
    const bool vok = vq < NV;
    const int vz = vq / 400, vy = (vq / 20) % 20, vx = vq % 20;
    const char* __restrict__ xpB = (const char*)g_xpair;
    const char* __restrict__ gAB = (const char*)g_A;

    auto load_tap = [&](int t, int s) {
        // W tile: 192 rows x 128B from g_A[t][n0c + row]
        const char* wsrc = gAB + (size_t)(t * MPAD + n0c) * 128;
#pragma unroll
        for (int i = 0; i < 6; i++) {
            int chunk = tid + (i << 8);            // 0..1535
            int row = chunk >> 3, cb = (chunk & 7) << 4;
            cp16(wbase[s] + sw128((row << 7) + cb), wsrc + (row << 7) + cb, true);
        }
        // X tile: 128 rows x 128B from g_xpair[shifted voxel]
        const int dz = t / 25 - 2, dy = (t / 5) % 5 - 2, dx = t % 5 - 2;
        const bool valid = vok && ((unsigned)(vz + dz) < 20u) &&
                           ((unsigned)(vy + dy) < 20u) && ((unsigned)(vx + dx) < 20u);
        const int vsrc = valid ? (vq + dz * 400 + dy * 20 + dx) : 0;
        const char* xsrc = xpB + (size_t)vsrc * 128;
#pragma unroll
        for (int i = 0; i < 4; i++) {
            int cb = (bh + i) << 4;
            cp16(xbase[s] + sw128((bn << 7) + cb), xsrc + cb, valid);
        }
    };

    float acc[4][6][4];
#pragma unroll
    for (int mf = 0; mf < 4; mf++)
#pragma unroll
        for (int nf = 0; nf < 6; nf++)
#pragma unroll
            for (int q = 0; q < 4; q++) acc[mf][nf][q] = 0.f;

    // ldmatrix per-thread address components
    const int x_row = wm * 64 + (lane & 15);      // + mf*16
    const int x_hi16 = (lane >> 4) << 4;          // 16B half select
    const int w_row = wn * 48 + (lane & 7);       // + nf*8
    const int w_hi16 = ((lane >> 3) & 1) << 4;    // k-half select (x2: lanes 0-15)

    // segment k-offsets (bytes): X: hi=0/32, lo=64/96 ; W likewise
    const int xseg[6] = {0, 32, 64, 96, 0, 32};
    const int wseg[6] = {0, 32, 0, 32, 64, 96};

    load_tap(0, 0);
    CP_COMMIT();

    for (int t = 0; t < 125; t++) {
        const int s = t & 1;
        if (t < 124) { load_tap(t + 1, s ^ 1); CP_COMMIT(); CP_WAIT(1); }
        else         { CP_WAIT(0); }
        __syncthreads();

        const uint32_t xb = xbase[s];
        const uint32_t wb = wbase[s];
#pragma unroll
        for (int seg = 0; seg < 6; seg++) {
            uint32_t af[4][4];
#pragma unroll
            for (int mf = 0; mf < 4; mf++)
                ldsm_x4(af[mf][0], af[mf][1], af[mf][2], af[mf][3],
                        xb + sw128(((x_row + mf * 16) << 7) + xseg[seg] + x_hi16));
            uint32_t bf[6][2];
#pragma unroll
            for (int nf = 0; nf < 6; nf++)
                ldsm_x2(bf[nf][0], bf[nf][1],
                        wb + sw128(((w_row + nf * 8) << 7) + wseg[seg] + w_hi16));
#pragma unroll
            for (int mf = 0; mf < 4; mf++)
#pragma unroll
                for (int nf = 0; nf < 6; nf++)
                    mma16816(acc[mf][nf], af[mf], bf[nf]);
        }
        __syncthreads();
    }

    // Epilogue: frag (mf,nf): c0 at (v = v0+wm*64+mf*16+lane/4,      o = n0c+wn*48+nf*8+(lane%4)*2)
    //                         c1 (v, o+1)   c2 (v+8, o)   c3 (v+8, o+1)
    const int vr = v0 + wm * 64 + (lane >> 2);
    const int ob = n0c + wn * 48 + (lane & 3) * 2;
#pragma unroll
    for (int nf = 0; nf < 6; nf++) {
        int o = ob + nf * 8;
        float bias0 = (o < MOUT) ? b_off[o] : 0.f;
        float bias1 = (o + 1 < MOUT) ? b_off[o + 1] : 0.f;
#pragma unroll
        for (int mf = 0; mf < 4; mf++) {
            int v1 = vr + mf * 16, v2 = v1 + 8;
            if (o < MOUT) {
                if (v1 < NV) g_off[o * NV + v1] = acc[mf][nf][0] + bias0;
                if (v2 < NV) g_off[o * NV + v2] = acc[mf][nf][2] + bias0;
            }
            if (o + 1 < MOUT) {
                if (v1 < NV) g_off[(o + 1) * NV + v1] = acc[mf][nf][1] + bias1;
                if (v2 < NV) g_off[(o + 1) * NV + v2] = acc[mf][nf][3] + bias1;
            }
        }
    }
}

// ---------------------------------------------------------------------------
// Stage B: deformable depthwise conv. Warp = 2 voxels; 16 lanes x 2 channels
// (float2). Halves per-output scalar math + load instruction count vs lane=ch.
// ---------------------------------------------------------------------------
__global__ __launch_bounds__(256) void deform_kernel(const float* __restrict__ b_dw) {
    const int lane = threadIdx.x & 31;
    const int sub = lane & 15;             // channel-pair index
    const int half = lane >> 4;            // voxel within warp
    const int v = blockIdx.x * 16 + (threadIdx.x >> 5) * 2 + half;
    const int vz = v / 400;
    const int vy = (v / 20) % 20;
    const int vx = v % 20;
    const float2* __restrict__ xt2 = (const float2*)g_xt;
    const float2* __restrict__ wd2 = (const float2*)g_wdwt;

    float2 acc = {0.f, 0.f};
#pragma unroll 1
    for (int kz = 0; kz < 5; kz++) {
#pragma unroll 1
        for (int ky = 0; ky < 5; ky++) {
#pragma unroll
            for (int kx = 0; kx < 5; kx++) {
                int t = (kz * 5 + ky) * 5 + kx;
                float oz = g_off[(t * 3 + 0) * NV + v];
                float oy = g_off[(t * 3 + 1) * NV + v];
                float ox = g_off[(t * 3 + 2) * NV + v];
                float pd = (float)(vz + kz - 2) + oz;
                float ph = (float)(vy + ky - 2) + oy;
                float pw = (float)(vx + kx - 2) + ox;
                float d0f = floorf(pd), h0f = floorf(ph), w0f = floorf(pw);
                float fd = pd - d0f, fh = ph - h0f, fw = pw - w0f;
                int d0 = (int)d0f, h0 = (int)h0f, w0 = (int)w0f;
                float wz0 = ((unsigned)d0       < 20u) ? (1.f - fd) : 0.f;
                float wz1 = ((unsigned)(d0 + 1) < 20u) ? fd         : 0.f;
                float wy0 = ((unsigned)h0       < 20u) ? (1.f - fh) : 0.f;
                float wy1 = ((unsigned)(h0 + 1) < 20u) ? fh         : 0.f;
                float wx0 = ((unsigned)w0       < 20u) ? (1.f - fw) : 0.f;
                float wx1 = ((unsigned)(w0 + 1) < 20u) ? fw         : 0.f;
                int iz0 = min(max(d0, 0), 19),     iz1 = min(max(d0 + 1, 0), 19);
                int iy0 = min(max(h0, 0), 19),     iy1 = min(max(h0 + 1, 0), 19);
                int ix0 = min(max(w0, 0), 19),     ix1 = min(max(w0 + 1, 0), 19);
                int r00 = (iz0 * 20 + iy0) * 20;
                int r01 = (iz0 * 20 + iy1) * 20;
                int r10 = (iz1 * 20 + iy0) * 20;
                int r11 = (iz1 * 20 + iy1) * 20;
                float2 x000 = xt2[(r00 + ix0) * 16 + sub];
                float2 x001 = xt2[(r00 + ix1) * 16 + sub];
                float2 x010 = xt2[(r01 + ix0) * 16 + sub];
                float2 x011 = xt2[(r01 + ix1) * 16 + sub];
                float2 x100 = xt2[(r10 + ix0) * 16 + sub];
                float2 x101 = xt2[(r10 + ix1) * 16 + sub];
                float2 x110 = xt2[(r11 + ix0) * 16 + sub];
                float2 x111 = xt2[(r11 + ix1) * 16 + sub];
                float w00 = wz0 * wy0, w01 = wz0 * wy1, w10 = wz1 * wy0, w11 = wz1 * wy1;
                float sx = w00 * (wx0 * x000.x + wx1 * x001.x) +
                           w01 * (wx0 * x010.x + wx1 * x011.x) +
                           w10 * (wx0 * x100.x + wx1 * x101.x) +
                           w11 * (wx0 * x110.x + wx1 * x111.x);
                float sy = w00 * (wx0 * x000.y + wx1 * x001.y) +
                           w01 * (wx0 * x010.y + wx1 * x011.y) +
                           w10 * (wx0 * x100.y + wx1 * x101.y) +
                           w11 * (wx0 * x110.y + wx1 * x111.y);
                float2 wt = wd2[t * 16 + sub];
                acc.x += wt.x * sx;
                acc.y += wt.y * sy;
            }
        }
    }
    float2 bias = ((const float2*)b_dw)[sub];
    acc.x += bias.x;
    acc.y += bias.y;
    ((float2*)g_attn1)[v * 16 + sub] = acc;
}

// ---------------------------------------------------------------------------
// Stage C: dilated (3) 7x7x7 depthwise conv, pad 9. Warp = 2 voxels,
// 16 lanes x 2 channels (float2).
// ---------------------------------------------------------------------------
__global__ __launch_bounds__(256) void spconv_kernel(const float* __restrict__ b_sp) {
    const int lane = threadIdx.x & 31;
    const int sub = lane & 15;
    const int half = lane >> 4;
    const int v = blockIdx.x * 16 + (threadIdx.x >> 5) * 2 + half;
    const int vz = v / 400;
    const int vy = (v / 20) % 20;
    const int vx = v % 20;
    const float2* __restrict__ a2 = (const float2*)g_attn1;
    const float2* __restrict__ w2 = (const float2*)g_wspt;

    float2 bias = ((const float2*)b_sp)[sub];
    float2 acc = bias;
#pragma unroll 1
    for (int kz = 0; kz < 7; kz++) {
        int zi = vz + kz * 3 - 9;
        if ((unsigned)zi >= 20u) continue;
#pragma unroll 1
        for (int ky = 0; ky < 7; ky++) {
            int yi = vy + ky * 3 - 9;
            if ((unsigned)yi >= 20u) continue;
            int rowbase = (zi * 20 + yi) * 20;
            int tbase = (kz * 7 + ky) * 7;
#pragma unroll
            for (int kx = 0; kx < 7; kx++) {
                int xi = vx + kx * 3 - 9;
                if ((unsigned)xi < 20u) {
                    float2 wv = w2[(tbase + kx) * 16 + sub];
                    float2 av = a2[(rowbase + xi) * 16 + sub];
                    acc.x += wv.x * av.x;
                    acc.y += wv.y * av.y;
                }
            }
        }
    }
    ((float2*)g_attn2)[v * 16 + sub] = acc;
}

// ---------------------------------------------------------------------------
// Stage D: 32x32 pointwise (+bias) fused with final x*attn, NCDHW output.
// ---------------------------------------------------------------------------
__global__ __launch_bounds__(256) void pw_kernel(const float* __restrict__ w_pw,
                                                 const float* __restrict__ b_pw,
                                                 const float* __restrict__ x,
                                                 float* __restrict__ out) {
    __shared__ float a_s[32][33];
    __shared__ float w_s[1024];
    const int tid = threadIdx.x;
    const int v0 = blockIdx.x * 32;
#pragma unroll
    for (int i = 0; i < 4; i++) {
        int e = tid + 256 * i;
        w_s[e] = w_pw[e];
        int vv = e >> 5, cc = e & 31;
        a_s[vv][cc] = g_attn2[v0 * 32 + e];
    }
    __syncthreads();

    const int lane = tid & 31;
    const int wq = tid >> 5;
#pragma unroll
    for (int i = 0; i < 4; i++) {
        int o = wq + 8 * i;
        float acc = b_pw[o];
#pragma unroll
        for (int c = 0; c < 32; c++)
            acc += w_s[o * 32 + c] * a_s[lane][c];
        int v = v0 + lane;
        out[o * NV + v] = x[o * NV + v] * acc;
    }
}

// ---------------------------------------------------------------------------
extern "C" void kernel_launch(void* const* d_in, const int* in_sizes, int n_in,
                              void* d_out, int out_size) {
    const float* x     = (const float*)d_in[0];
    const float* w_off = (const float*)d_in[1];
    const float* b_off = (const float*)d_in[2];
    const float* w_dw  = (const float*)d_in[3];
    const float* b_dw  = (const float*)d_in[4];
    const float* w_sp  = (const float*)d_in[5];
    const float* b_sp  = (const float*)d_in[6];
    const float* w_pw  = (const float*)d_in[7];
    const float* b_pw  = (const float*)d_in[8];
    float* out = (float*)d_out;

    cudaFuncSetAttribute(gemm_off_kernel,
                         cudaFuncAttributeMaxDynamicSharedMemorySize, SMEM_SZ);

    prep_kernel<<<2000, 256>>>(x, w_dw, w_sp);
    prep_a_kernel<<<MPAD, 256>>>(w_off);               // 1 block per out-row
    dim3 gg(63, 2);                                    // 63 v-tiles x 2 n-tiles
    gemm_off_kernel<<<gg, 256, SMEM_SZ>>>(b_off);
    deform_kernel<<<500, 256>>>(b_dw);
    spconv_kernel<<<500, 256>>>(b_sp);
    pw_kernel<<<250, 256>>>(w_pw, b_pw, x, out);
}

// round 9
// speedup vs baseline: 2.5665x; 1.0353x over previous
#include <cuda_runtime.h>
#include <cuda_bf16.h>
#include <cstdint>

// Problem constants: B=1, C=32, S=20, K=5 (125 taps), offset conv out = 375 ch.
#define NV   8000     // 20^3 voxels
#define NC   32       // channels
#define MOUT 375      // 3*K3 offset channels
#define MPAD 384      // padded to 2 x 192 n-tiles

// Scratch (static device globals — no allocation APIs allowed)
__device__ float g_offv[NV * 384];     // offsets, [v][o]  (padded to 384)
__device__ float g_xt[NV * NC];        // x transposed to [v][c]
__device__ float g_attn1[NV * NC];     // deform output, [v][c]
__device__ float g_attn2[NV * NC];     // dilated depthwise output, [v][c]
__device__ float g_wdwt[125 * NC];     // w_dw transposed [t][c]
__device__ float g_wspt[343 * NC];     // w_sp transposed [t][c]
// bf16-split operands for the HMMA offset GEMM
__device__ __align__(16) __nv_bfloat16 g_A[125 * MPAD * 64];  // per tap: [m][hi c0..31 | lo c0..31]
__device__ __align__(16) __nv_bfloat16 g_xpair[NV * 64];      // per voxel: [hi c0..31 | lo c0..31]

__device__ __forceinline__ uint32_t smem_u32(const void* p) {
    uint32_t a;
    asm("{ .reg .u64 t; cvta.to.shared.u64 t, %1; cvt.u32.u64 %0, t; }" : "=r"(a) : "l"(p));
    return a;
}
__device__ __forceinline__ uint32_t sw128(uint32_t off) { return off ^ ((off >> 3) & 0x70); }

// cp.async 16B with zero-fill predication (src-size = 0 skips the read)
__device__ __forceinline__ void cp16(uint32_t dst, const void* src, bool pred) {
    int sz = pred ? 16 : 0;
    asm volatile("cp.async.cg.shared.global [%0], [%1], 16, %2;" :: "r"(dst), "l"(src), "r"(sz));
}
#define CP_COMMIT() asm volatile("cp.async.commit_group;" ::: "memory")
#define CP_WAIT(N)  asm volatile("cp.async.wait_group %0;" :: "n"(N) : "memory")

__device__ __forceinline__ void ldsm_x4(uint32_t& r0, uint32_t& r1, uint32_t& r2,
                                        uint32_t& r3, uint32_t addr) {
    asm volatile("ldmatrix.sync.aligned.m8n8.x4.shared.b16 {%0,%1,%2,%3}, [%4];"
                 : "=r"(r0), "=r"(r1), "=r"(r2), "=r"(r3) : "r"(addr));
}
__device__ __forceinline__ void mma16816(float* c, const uint32_t* a, const uint32_t* b) {
    asm volatile("mma.sync.aligned.m16n8k16.row.col.f32.bf16.bf16.f32 "
                 "{%0,%1,%2,%3}, {%4,%5,%6,%7}, {%8,%9}, {%0,%1,%2,%3};"
                 : "+f"(c[0]), "+f"(c[1]), "+f"(c[2]), "+f"(c[3])
                 : "r"(a[0]), "r"(a[1]), "r"(a[2]), "r"(a[3]), "r"(b[0]), "r"(b[1]));
}

// ---------------------------------------------------------------------------
// Prep: transposes + bf16 hi/lo split of x ([v][hi c|lo c])
// ---------------------------------------------------------------------------
__global__ __launch_bounds__(256) void prep_kernel(const float* __restrict__ x,
                                                   const float* __restrict__ w_dw,
                                                   const float* __restrict__ w_sp) {
    int idx = blockIdx.x * blockDim.x + threadIdx.x;
    if (idx < NV * 64) {  // g_xpair
        int v = idx >> 6, j = idx & 63, c = j & 31;
        float val = x[c * NV + v];
        __nv_bfloat16 hi = __float2bfloat16(val);
        g_xpair[idx] = (j < 32) ? hi : __float2bfloat16(val - __bfloat162float(hi));
    }
    if (idx < NV * NC) {
        int v = idx >> 5, c = idx & 31;
        g_xt[idx] = x[c * NV + v];
    }
    if (idx < 125 * NC) {
        int t = idx >> 5, c = idx & 31;
        g_wdwt[idx] = w_dw[c * 125 + t];
    }
    if (idx < 343 * NC) {
        int t = idx >> 5, c = idx & 31;
        g_wspt[idx] = w_sp[c * 343 + t];
    }
}

// Prep A (coalesced): one block per output row m.
__global__ __launch_bounds__(256) void prep_a_kernel(const float* __restrict__ w_off) {
    __shared__ float row[4000];
    const int m = blockIdx.x;
    const int tid = threadIdx.x;
    const bool mok = m < MOUT;
    if (mok)
        for (int i = tid; i < 4000; i += 256) row[i] = w_off[m * 4000 + i];
    __syncthreads();
    const int lane = tid & 31;
    const int wq = tid >> 5;
    for (int t = wq; t < 125; t += 8) {
        float wv = mok ? row[lane * 125 + t] : 0.f;
        __nv_bfloat16 hi = __float2bfloat16(wv);
        __nv_bfloat16 lo = __float2bfloat16(wv - __bfloat162float(hi));
        size_t base = ((size_t)t * MPAD + m) * 64;
        g_A[base + lane] = hi;
        g_A[base + 32 + lane] = lo;
    }
}

// ---------------------------------------------------------------------------
// Stage A: offset conv as 125 tap-GEMMs via mma.sync bf16.
// CTA = 128 voxels x 192 out-ch, 8 warps (2m x 4n), warp tile 64v x 48o.
// Per tap: segments (xoff,woff) in {(0,0),(64,0),(32,32),(96,32),(0,64),(32,96)}
// with A(0)/A(32) loaded once and reused; B loaded via x4 pair-loads.
// ---------------------------------------------------------------------------
#define WS0 0
#define WS1 24576
#define XS0 49152
#define XS1 65536
#define SMEM_SZ 81920

__global__ __launch_bounds__(256, 1) void gemm_off_kernel(const float* __restrict__ b_off) {
    extern __shared__ __align__(1024) char smem[];
    const uint32_t sb = smem_u32(smem);
    const int tid = threadIdx.x;
    const int lane = tid & 31;
    const int w = tid >> 5;
    const int wm = w & 1;          // m half (64 voxels)
    const int wn = w >> 1;         // n quarter (48 ch)
    const int v0 = blockIdx.x * 128;
    const int n0c = blockIdx.y * 192;

    const uint32_t wbase[2] = {sb + WS0, sb + WS1};
    const uint32_t xbase[2] = {sb + XS0, sb + XS1};

    // X fill mapping: 2 threads per voxel row
    const int bn = tid >> 1;             // row 0..127
    const int bh = (tid & 1) * 4;        // 16B-chunk base
    const int vq = v0 + bn;
    const bool vok = vq < NV;
    const int vz = vq / 400, vy = (vq / 20) % 20, vx = vq % 20;
    const char* __restrict__ xpB = (const char*)g_xpair;
    const char* __restrict__ gAB = (const char*)g_A;

    auto load_tap = [&](int t, int s) {
        // W tile: 192 rows x 128B from g_A[t][n0c + row]
        const char* wsrc = gAB + (size_t)(t * MPAD + n0c) * 128;
#pragma unroll
        for (int i = 0; i < 6; i++) {
            int chunk = tid + (i << 8);            // 0..1535
            int row = chunk >> 3, cb = (chunk & 7) << 4;
            cp16(wbase[s] + sw128((row << 7) + cb), wsrc + (row << 7) + cb, true);
        }
        // X tile: 128 rows x 128B from g_xpair[shifted voxel]
        const int dz = t / 25 - 2, dy = (t / 5) % 5 - 2, dx = t % 5 - 2;
        const bool valid = vok && ((unsigned)(vz + dz) < 20u) &&
                           ((unsigned)(vy + dy) < 20u) && ((unsigned)(vx + dx) < 20u);
        const int vsrc = valid ? (vq + dz * 400 + dy * 20 + dx) : 0;
        const char* xsrc = xpB + (size_t)vsrc * 128;
#pragma unroll
        for (int i = 0; i < 4; i++) {
            int cb = (bh + i) << 4;
            cp16(xbase[s] + sw128((bn << 7) + cb), xsrc + cb, valid);
        }
    };

    float acc[4][6][4];
#pragma unroll
    for (int mf = 0; mf < 4; mf++)
#pragma unroll
        for (int nf = 0; nf < 6; nf++)
#pragma unroll
            for (int q = 0; q < 4; q++) acc[mf][nf][q] = 0.f;

    // ldmatrix per-thread address components
    const int x_row = wm * 64 + (lane & 15);               // + mf*16
    const int x_hi16 = (lane >> 4) << 4;                   // 16B half select
    const int w_row4 = wn * 48 + ((lane >> 4) << 3) + (lane & 7);  // + p*16
    const int w_k16 = ((lane >> 3) & 1) << 4;              // k-half select

    auto loadA = [&](uint32_t (*f)[4], uint32_t xb, int xoff) {
#pragma unroll
        for (int mf = 0; mf < 4; mf++)
            ldsm_x4(f[mf][0], f[mf][1], f[mf][2], f[mf][3],
                    xb + sw128(((x_row + mf * 16) << 7) + xoff + x_hi16));
    };
    auto loadB = [&](uint32_t (*f)[2], uint32_t wb, int woff) {
#pragma unroll
        for (int p = 0; p < 3; p++) {
            uint32_t r0, r1, r2, r3;
            ldsm_x4(r0, r1, r2, r3,
                    wb + sw128(((w_row4 + p * 16) << 7) + woff + w_k16));
            f[2 * p][0] = r0;     f[2 * p][1] = r1;
            f[2 * p + 1][0] = r2; f[2 * p + 1][1] = r3;
        }
    };
    auto mmaSeg = [&](uint32_t (*a)[4], uint32_t (*b)[2]) {
#pragma unroll
        for (int mf = 0; mf < 4; mf++)
#pragma unroll
            for (int nf = 0; nf < 6; nf++)
                mma16816(acc[mf][nf], a[mf], b[nf]);
    };

    load_tap(0, 0);
    CP_COMMIT();

    for (int t = 0; t < 125; t++) {
        const int s = t & 1;
        if (t < 124) { load_tap(t + 1, s ^ 1); CP_COMMIT(); CP_WAIT(1); }
        else         { CP_WAIT(0); }
        __syncthreads();

        const uint32_t xb = xbase[s];
        const uint32_t wb = wbase[s];
        uint32_t Ah0[4][4], Ah1[4][4], Al[4][4], B[6][2];
        loadB(B, wb, 0);  loadA(Ah0, xb, 0);  mmaSeg(Ah0, B);   // Xh0*Wh0
        loadA(Al, xb, 64);                     mmaSeg(Al, B);    // Xl0*Wh0
        loadB(B, wb, 32); loadA(Ah1, xb, 32); mmaSeg(Ah1, B);   // Xh1*Wh1
        loadA(Al, xb, 96);                     mmaSeg(Al, B);    // Xl1*Wh1
        loadB(B, wb, 64);                      mmaSeg(Ah0, B);   // Xh0*Wl0
        loadB(B, wb, 96);                      mmaSeg(Ah1, B);   // Xh1*Wl1
        __syncthreads();
    }

    // Epilogue: write g_offv [v][384] (cols >= MOUT are dead padding).
    const int vr = v0 + wm * 64 + (lane >> 2);
    const int ob = n0c + wn * 48 + (lane & 3) * 2;
#pragma unroll
    for (int nf = 0; nf < 6; nf++) {
        int o = ob + nf * 8;
        float bias0 = (o < MOUT) ? b_off[o] : 0.f;
        float bias1 = (o + 1 < MOUT) ? b_off[o + 1] : 0.f;
#pragma unroll
        for (int mf = 0; mf < 4; mf++) {
            int v1 = vr + mf * 16, v2 = v1 + 8;
            if (v1 < NV) {
                float2 r = {acc[mf][nf][0] + bias0, acc[mf][nf][1] + bias1};
                *(float2*)&g_offv[(size_t)v1 * 384 + o] = r;
            }
            if (v2 < NV) {
                float2 r = {acc[mf][nf][2] + bias0, acc[mf][nf][3] + bias1};
                *(float2*)&g_offv[(size_t)v2 * 384 + o] = r;
            }
        }
    }
}

// ---------------------------------------------------------------------------
// Stage B: deformable depthwise conv. Warp = 2 voxels; 16 lanes x 2 channels.
// Offsets staged to smem via coalesced float4 loads ([v][384] layout).
// ---------------------------------------------------------------------------
__global__ __launch_bounds__(256) void deform_kernel(const float* __restrict__ b_dw) {
    __shared__ float s_off[16 * 384];
    const int tid = threadIdx.x;
    const int lane = tid & 31;
    const int warp = tid >> 5;
    const int sub = lane & 15;             // channel-pair index
    const int half = lane >> 4;            // voxel within warp
    const int vbase = blockIdx.x * 16;

    // stage this warp's 2 voxels of offsets (768 floats = 192 float4)
    {
        const float4* src = (const float4*)(g_offv + (size_t)(vbase + warp * 2) * 384);
        float4* dst = (float4*)(s_off + warp * 2 * 384);
#pragma unroll
        for (int i = 0; i < 6; i++) dst[lane + 32 * i] = src[lane + 32 * i];
    }
    __syncwarp();

    const int v = vbase + warp * 2 + half;
    const int vz = v / 400;
    const int vy = (v / 20) % 20;
    const int vx = v % 20;
    const float* __restrict__ off = s_off + (warp * 2 + half) * 384;
    const float2* __restrict__ xt2 = (const float2*)g_xt;
    const float2* __restrict__ wd2 = (const float2*)g_wdwt;

    float2 acc = {0.f, 0.f};
#pragma unroll 1
    for (int kz = 0; kz < 5; kz++) {
#pragma unroll 1
        for (int ky = 0; ky < 5; ky++) {
#pragma unroll
            for (int kx = 0; kx < 5; kx++) {
                int t = (kz * 5 + ky) * 5 + kx;
                float oz = off[t * 3 + 0];
                float oy = off[t * 3 + 1];
                float ox = off[t * 3 + 2];
                float pd = (float)(vz + kz - 2) + oz;
                float ph = (float)(vy + ky - 2) + oy;
                float pw = (float)(vx + kx - 2) + ox;
                float d0f = floorf(pd), h0f = floorf(ph), w0f = floorf(pw);
                float fd = pd - d0f, fh = ph - h0f, fw = pw - w0f;
                int d0 = (int)d0f, h0 = (int)h0f, w0 = (int)w0f;
                float wz0 = ((unsigned)d0       < 20u) ? (1.f - fd) : 0.f;
                float wz1 = ((unsigned)(d0 + 1) < 20u) ? fd         : 0.f;
                float wy0 = ((unsigned)h0       < 20u) ? (1.f - fh) : 0.f;
                float wy1 = ((unsigned)(h0 + 1) < 20u) ? fh         : 0.f;
                float wx0 = ((unsigned)w0       < 20u) ? (1.f - fw) : 0.f;
                float wx1 = ((unsigned)(w0 + 1) < 20u) ? fw         : 0.f;
                int iz0 = min(max(d0, 0), 19),     iz1 = min(max(d0 + 1, 0), 19);
                int iy0 = min(max(h0, 0), 19),     iy1 = min(max(h0 + 1, 0), 19);
                int ix0 = min(max(w0, 0), 19),     ix1 = min(max(w0 + 1, 0), 19);
                int r00 = (iz0 * 20 + iy0) * 20;
                int r01 = (iz0 * 20 + iy1) * 20;
                int r10 = (iz1 * 20 + iy0) * 20;
                int r11 = (iz1 * 20 + iy1) * 20;
                float2 x000 = xt2[(r00 + ix0) * 16 + sub];
                float2 x001 = xt2[(r00 + ix1) * 16 + sub];
                float2 x010 = xt2[(r01 + ix0) * 16 + sub];
                float2 x011 = xt2[(r01 + ix1) * 16 + sub];
                float2 x100 = xt2[(r10 + ix0) * 16 + sub];
                float2 x101 = xt2[(r10 + ix1) * 16 + sub];
                float2 x110 = xt2[(r11 + ix0) * 16 + sub];
                float2 x111 = xt2[(r11 + ix1) * 16 + sub];
                float w00 = wz0 * wy0, w01 = wz0 * wy1, w10 = wz1 * wy0, w11 = wz1 * wy1;
                float sx = w00 * (wx0 * x000.x + wx1 * x001.x) +
                           w01 * (wx0 * x010.x + wx1 * x011.x) +
                           w10 * (wx0 * x100.x + wx1 * x101.x) +
                           w11 * (wx0 * x110.x + wx1 * x111.x);
                float sy = w00 * (wx0 * x000.y + wx1 * x001.y) +
                           w01 * (wx0 * x010.y + wx1 * x011.y) +
                           w10 * (wx0 * x100.y + wx1 * x101.y) +
                           w11 * (wx0 * x110.y + wx1 * x111.y);
                float2 wt = wd2[t * 16 + sub];
                acc.x += wt.x * sx;
                acc.y += wt.y * sy;
            }
        }
    }
    float2 bias = ((const float2*)b_dw)[sub];
    acc.x += bias.x;
    acc.y += bias.y;
    ((float2*)g_attn1)[v * 16 + sub] = acc;
}

// ---------------------------------------------------------------------------
// Stage C: dilated (3) 7x7x7 depthwise conv, pad 9. Warp = 2 voxels,
// 16 lanes x 2 channels (float2).
// ---------------------------------------------------------------------------
__global__ __launch_bounds__(256) void spconv_kernel(const float* __restrict__ b_sp) {
    const int lane = threadIdx.x & 31;
    const int sub = lane & 15;
    const int half = lane >> 4;
    const int v = blockIdx.x * 16 + (threadIdx.x >> 5) * 2 + half;
    const int vz = v / 400;
    const int vy = (v / 20) % 20;
    const int vx = v % 20;
    const float2* __restrict__ a2 = (const float2*)g_attn1;
    const float2* __restrict__ w2 = (const float2*)g_wspt;

    float2 bias = ((const float2*)b_sp)[sub];
    float2 acc = bias;
#pragma unroll 1
    for (int kz = 0; kz < 7; kz++) {
        int zi = vz + kz * 3 - 9;
        if ((unsigned)zi >= 20u) continue;
#pragma unroll 1
        for (int ky = 0; ky < 7; ky++) {
            int yi = vy + ky * 3 - 9;
            if ((unsigned)yi >= 20u) continue;
            int rowbase = (zi * 20 + yi) * 20;
            int tbase = (kz * 7 + ky) * 7;
#pragma unroll
            for (int kx = 0; kx < 7; kx++) {
                int xi = vx + kx * 3 - 9;
                if ((unsigned)xi < 20u) {
                    float2 wv = w2[(tbase + kx) * 16 + sub];
                    float2 av = a2[(rowbase + xi) * 16 + sub];
                    acc.x += wv.x * av.x;
                    acc.y += wv.y * av.y;
                }
            }
        }
    }
    ((float2*)g_attn2)[v * 16 + sub] = acc;
}

// ---------------------------------------------------------------------------
// Stage D: 32x32 pointwise (+bias) fused with final x*attn, NCDHW output.
// ---------------------------------------------------------------------------
__global__ __launch_bounds__(256) void pw_kernel(const float* __restrict__ w_pw,
                                                 const float* __restrict__ b_pw,
                                                 const float* __restrict__ x,
                                                 float* __restrict__ out) {
    __shared__ float a_s[32][33];
    __shared__ float w_s[1024];
    const int tid = threadIdx.x;
    const int v0 = blockIdx.x * 32;
#pragma unroll
    for (int i = 0; i < 4; i++) {
        int e = tid + 256 * i;
        w_s[e] = w_pw[e];
        int vv = e >> 5, cc = e & 31;
        a_s[vv][cc] = g_attn2[v0 * 32 + e];
    }
    __syncthreads();

    const int lane = tid & 31;
    const int wq = tid >> 5;
#pragma unroll
    for (int i = 0; i < 4; i++) {
        int o = wq + 8 * i;
        float acc = b_pw[o];
#pragma unroll
        for (int c = 0; c < 32; c++)
            acc += w_s[o * 32 + c] * a_s[lane][c];
        int v = v0 + lane;
        out[o * NV + v] = x[o * NV + v] * acc;
    }
}

// ---------------------------------------------------------------------------
extern "C" void kernel_launch(void* const* d_in, const int* in_sizes, int n_in,
                              void* d_out, int out_size) {
    const float* x     = (const float*)d_in[0];
    const float* w_off = (const float*)d_in[1];
    const float* b_off = (const float*)d_in[2];
    const float* w_dw  = (const float*)d_in[3];
    const float* b_dw  = (const float*)d_in[4];
    const float* w_sp  = (const float*)d_in[5];
    const float* b_sp  = (const float*)d_in[6];
    const float* w_pw  = (const float*)d_in[7];
    const float* b_pw  = (const float*)d_in[8];
    float* out = (float*)d_out;

    cudaFuncSetAttribute(gemm_off_kernel,
                         cudaFuncAttributeMaxDynamicSharedMemorySize, SMEM_SZ);

    prep_kernel<<<2000, 256>>>(x, w_dw, w_sp);
    prep_a_kernel<<<MPAD, 256>>>(w_off);               // 1 block per out-row
    dim3 gg(63, 2);                                    // 63 v-tiles x 2 n-tiles
    gemm_off_kernel<<<gg, 256, SMEM_SZ>>>(b_off);
    deform_kernel<<<500, 256>>>(b_dw);
    spconv_kernel<<<500, 256>>>(b_sp);
    pw_kernel<<<250, 256>>>(w_pw, b_pw, x, out);
}

// round 11
// speedup vs baseline: 2.7379x; 1.0668x over previous
#include <cuda_runtime.h>
#include <cuda_bf16.h>
#include <cstdint>

// Problem constants: B=1, C=32, S=20, K=5 (125 taps), offset conv out = 375 ch.
#define NV   8000     // 20^3 voxels
#define NC   32       // channels
#define MOUT 375      // 3*K3 offset channels
#define MPAD 384      // padded to 2 x 192 n-tiles

// Scratch (static device globals — no allocation APIs allowed)
__device__ __align__(16) float g_offv[NV * 384];   // offsets, [v][o] (padded)
__device__ __align__(16) float g_xt[NV * NC];      // x transposed to [v][c]
__device__ __align__(16) float g_attn1[NV * NC];   // deform output, [v][c]
__device__ __align__(16) float g_attn2[NV * NC];   // dilated depthwise output, [v][c]
__device__ __align__(16) float g_wdwt[125 * NC];   // w_dw transposed [t][c]
__device__ __align__(16) float g_wspt[343 * NC];   // w_sp transposed [t][c]
// bf16-split operands for the HMMA offset GEMM
__device__ __align__(16) __nv_bfloat16 g_A[125 * MPAD * 64];  // per tap: [m][hi c0..31 | lo c0..31]
__device__ __align__(16) __nv_bfloat16 g_xpair[NV * 64];      // per voxel: [hi c0..31 | lo c0..31]

__device__ __forceinline__ uint32_t smem_u32(const void* p) {
    uint32_t a;
    asm("{ .reg .u64 t; cvta.to.shared.u64 t, %1; cvt.u32.u64 %0, t; }" : "=r"(a) : "l"(p));
    return a;
}
__device__ __forceinline__ uint32_t sw128(uint32_t off) { return off ^ ((off >> 3) & 0x70); }

// cp.async 16B with zero-fill predication (src-size = 0 skips the read)
__device__ __forceinline__ void cp16(uint32_t dst, const void* src, bool pred) {
    int sz = pred ? 16 : 0;
    asm volatile("cp.async.cg.shared.global [%0], [%1], 16, %2;" :: "r"(dst), "l"(src), "r"(sz));
}
#define CP_COMMIT() asm volatile("cp.async.commit_group;" ::: "memory")
#define CP_WAIT(N)  asm volatile("cp.async.wait_group %0;" :: "n"(N) : "memory")

__device__ __forceinline__ void ldsm_x4(uint32_t& r0, uint32_t& r1, uint32_t& r2,
                                        uint32_t& r3, uint32_t addr) {
    asm volatile("ldmatrix.sync.aligned.m8n8.x4.shared.b16 {%0,%1,%2,%3}, [%4];"
                 : "=r"(r0), "=r"(r1), "=r"(r2), "=r"(r3) : "r"(addr));
}
__device__ __forceinline__ void mma16816(float* c, const uint32_t* a, const uint32_t* b) {
    asm volatile("mma.sync.aligned.m16n8k16.row.col.f32.bf16.bf16.f32 "
                 "{%0,%1,%2,%3}, {%4,%5,%6,%7}, {%8,%9}, {%0,%1,%2,%3};"
                 : "+f"(c[0]), "+f"(c[1]), "+f"(c[2]), "+f"(c[3])
                 : "r"(a[0]), "r"(a[1]), "r"(a[2]), "r"(a[3]), "r"(b[0]), "r"(b[1]));
}

// ---------------------------------------------------------------------------
// Prep: transposes + bf16 hi/lo split of x ([v][hi c|lo c])
// ---------------------------------------------------------------------------
__global__ __launch_bounds__(256) void prep_kernel(const float* __restrict__ x,
                                                   const float* __restrict__ w_dw,
                                                   const float* __restrict__ w_sp) {
    int idx = blockIdx.x * blockDim.x + threadIdx.x;
    if (idx < NV * 64) {  // g_xpair
        int v = idx >> 6, j = idx & 63, c = j & 31;
        float val = x[c * NV + v];
        __nv_bfloat16 hi = __float2bfloat16(val);
        g_xpair[idx] = (j < 32) ? hi : __float2bfloat16(val - __bfloat162float(hi));
    }
    if (idx < NV * NC) {
        int v = idx >> 5, c = idx & 31;
        g_xt[idx] = x[c * NV + v];
    }
    if (idx < 125 * NC) {
        int t = idx >> 5, c = idx & 31;
        g_wdwt[idx] = w_dw[c * 125 + t];
    }
    if (idx < 343 * NC) {
        int t = idx >> 5, c = idx & 31;
        g_wspt[idx] = w_sp[c * 343 + t];
    }
}

// Prep A (coalesced): one block per output row m.
__global__ __launch_bounds__(256) void prep_a_kernel(const float* __restrict__ w_off) {
    __shared__ float row[4000];
    const int m = blockIdx.x;
    const int tid = threadIdx.x;
    const bool mok = m < MOUT;
    if (mok)
        for (int i = tid; i < 4000; i += 256) row[i] = w_off[m * 4000 + i];
    __syncthreads();
    const int lane = tid & 31;
    const int wq = tid >> 5;
    for (int t = wq; t < 125; t += 8) {
        float wv = mok ? row[lane * 125 + t] : 0.f;
        __nv_bfloat16 hi = __float2bfloat16(wv);
        __nv_bfloat16 lo = __float2bfloat16(wv - __bfloat162float(hi));
        size_t base = ((size_t)t * MPAD + m) * 64;
        g_A[base + lane] = hi;
        g_A[base + 32 + lane] = lo;
    }
}

// ---------------------------------------------------------------------------
// Stage A: offset conv as 125 tap-GEMMs via mma.sync bf16. (unchanged)
// ---------------------------------------------------------------------------
#define WS0 0
#define WS1 24576
#define XS0 49152
#define XS1 65536
#define SMEM_SZ 81920

__global__ __launch_bounds__(256, 1) void gemm_off_kernel(const float* __restrict__ b_off) {
    extern __shared__ __align__(1024) char smem[];
    const uint32_t sb = smem_u32(smem);
    const int tid = threadIdx.x;
    const int lane = tid & 31;
    const int w = tid >> 5;
    const int wm = w & 1;          // m half (64 voxels)
    const int wn = w >> 1;         // n quarter (48 ch)
    const int v0 = blockIdx.x * 128;
    const int n0c = blockIdx.y * 192;

    const uint32_t wbase[2] = {sb + WS0, sb + WS1};
    const uint32_t xbase[2] = {sb + XS0, sb + XS1};

    const int bn = tid >> 1;             // row 0..127
    const int bh = (tid & 1) * 4;        // 16B-chunk base
    const int vq = v0 + bn;
    const bool vok = vq < NV;
    const int vz = vq / 400, vy = (vq / 20) % 20, vx = vq % 20;
    const char* __restrict__ xpB = (const char*)g_xpair;
    const char* __restrict__ gAB = (const char*)g_A;

    auto load_tap = [&](int t, int s) {
        const char* wsrc = gAB + (size_t)(t * MPAD + n0c) * 128;
#pragma unroll
        for (int i = 0; i < 6; i++) {
            int chunk = tid + (i << 8);
            int row = chunk >> 3, cb = (chunk & 7) << 4;
            cp16(wbase[s] + sw128((row << 7) + cb), wsrc + (row << 7) + cb, true);
        }
        const int dz = t / 25 - 2, dy = (t / 5) % 5 - 2, dx = t % 5 - 2;
        const bool valid = vok && ((unsigned)(vz + dz) < 20u) &&
                           ((unsigned)(vy + dy) < 20u) && ((unsigned)(vx + dx) < 20u);
        const int vsrc = valid ? (vq + dz * 400 + dy * 20 + dx) : 0;
        const char* xsrc = xpB + (size_t)vsrc * 128;
#pragma unroll
        for (int i = 0; i < 4; i++) {
            int cb = (bh + i) << 4;
            cp16(xbase[s] + sw128((bn << 7) + cb), xsrc + cb, valid);
        }
    };

    float acc[4][6][4];
#pragma unroll
    for (int mf = 0; mf < 4; mf++)
#pragma unroll
        for (int nf = 0; nf < 6; nf++)
#pragma unroll
            for (int q = 0; q < 4; q++) acc[mf][nf][q] = 0.f;

    const int x_row = wm * 64 + (lane & 15);
    const int x_hi16 = (lane >> 4) << 4;
    const int w_row4 = wn * 48 + ((lane >> 4) << 3) + (lane & 7);
    const int w_k16 = ((lane >> 3) & 1) << 4;

    auto loadA = [&](uint32_t (*f)[4], uint32_t xb, int xoff) {
#pragma unroll
        for (int mf = 0; mf < 4; mf++)
            ldsm_x4(f[mf][0], f[mf][1], f[mf][2], f[mf][3],
                    xb + sw128(((x_row + mf * 16) << 7) + xoff + x_hi16));
    };
    auto loadB = [&](uint32_t (*f)[2], uint32_t wb, int woff) {
#pragma unroll
        for (int p = 0; p < 3; p++) {
            uint32_t r0, r1, r2, r3;
            ldsm_x4(r0, r1, r2, r3,
                    wb + sw128(((w_row4 + p * 16) << 7) + woff + w_k16));
            f[2 * p][0] = r0;     f[2 * p][1] = r1;
            f[2 * p + 1][0] = r2; f[2 * p + 1][1] = r3;
        }
    };
    auto mmaSeg = [&](uint32_t (*a)[4], uint32_t (*b)[2]) {
#pragma unroll
        for (int mf = 0; mf < 4; mf++)
#pragma unroll
            for (int nf = 0; nf < 6; nf++)
                mma16816(acc[mf][nf], a[mf], b[nf]);
    };

    load_tap(0, 0);
    CP_COMMIT();

    for (int t = 0; t < 125; t++) {
        const int s = t & 1;
        if (t < 124) { load_tap(t + 1, s ^ 1); CP_COMMIT(); CP_WAIT(1); }
        else         { CP_WAIT(0); }
        __syncthreads();

        const uint32_t xb = xbase[s];
        const uint32_t wb = wbase[s];
        uint32_t Ah0[4][4], Ah1[4][4], Al[4][4], B[6][2];
        loadB(B, wb, 0);  loadA(Ah0, xb, 0);  mmaSeg(Ah0, B);
        loadA(Al, xb, 64);                     mmaSeg(Al, B);
        loadB(B, wb, 32); loadA(Ah1, xb, 32); mmaSeg(Ah1, B);
        loadA(Al, xb, 96);                     mmaSeg(Al, B);
        loadB(B, wb, 64);                      mmaSeg(Ah0, B);
        loadB(B, wb, 96);                      mmaSeg(Ah1, B);
        __syncthreads();
    }

    const int vr = v0 + wm * 64 + (lane >> 2);
    const int ob = n0c + wn * 48 + (lane & 3) * 2;
#pragma unroll
    for (int nf = 0; nf < 6; nf++) {
        int o = ob + nf * 8;
        float bias0 = (o < MOUT) ? b_off[o] : 0.f;
        float bias1 = (o + 1 < MOUT) ? b_off[o + 1] : 0.f;
#pragma unroll
        for (int mf = 0; mf < 4; mf++) {
            int v1 = vr + mf * 16, v2 = v1 + 8;
            if (v1 < NV) {
                float2 r = {acc[mf][nf][0] + bias0, acc[mf][nf][1] + bias1};
                *(float2*)&g_offv[(size_t)v1 * 384 + o] = r;
            }
            if (v2 < NV) {
                float2 r = {acc[mf][nf][2] + bias0, acc[mf][nf][3] + bias1};
                *(float2*)&g_offv[(size_t)v2 * 384 + o] = r;
            }
        }
    }
}

// ---------------------------------------------------------------------------
// Stage B: deformable depthwise conv. Warp = 4 voxels; 8 lanes x 4 channels
// (float4). Flat 8-corner-weight interp; independent corner clamps.
// ---------------------------------------------------------------------------
__global__ __launch_bounds__(128) void deform_kernel(const float* __restrict__ b_dw) {
    __shared__ __align__(16) float s_off[16 * 384];
    const int tid = threadIdx.x;
    const int lane = tid & 31;
    const int warp = tid >> 5;             // 0..3
    const int sub = lane & 7;              // channel-quad index
    const int qv = lane >> 3;              // voxel within warp (0..3)
    const int vbase = blockIdx.x * 16;

    // stage this warp's 4 voxels of offsets (1536 floats = 384 float4)
    {
        const float4* src = (const float4*)(g_offv + (size_t)(vbase + warp * 4) * 384);
        float4* dst = (float4*)(s_off + warp * 4 * 384);
#pragma unroll
        for (int i = 0; i < 12; i++) dst[lane + 32 * i] = src[lane + 32 * i];
    }
    __syncwarp();

    const int v = vbase + warp * 4 + qv;
    const int vz = v / 400;
    const int vy = (v / 20) % 20;
    const int vx = v % 20;
    const float* __restrict__ off = s_off + (warp * 4 + qv) * 384;
    const float4* __restrict__ xt4 = (const float4*)g_xt;
    const float4* __restrict__ wd4 = (const float4*)g_wdwt;

    float4 acc = {0.f, 0.f, 0.f, 0.f};
#pragma unroll 1
    for (int kz = 0; kz < 5; kz++) {
        const float fz = (float)(vz + kz - 2);
#pragma unroll 1
        for (int ky = 0; ky < 5; ky++) {
            const float fy = (float)(vy + ky - 2);
#pragma unroll
            for (int kx = 0; kx < 5; kx++) {
                int t = (kz * 5 + ky) * 5 + kx;
                float pd = fz + off[t * 3 + 0];
                float ph = fy + off[t * 3 + 1];
                float pw = (float)(vx + kx - 2) + off[t * 3 + 2];
                float d0f = floorf(pd), h0f = floorf(ph), w0f = floorf(pw);
                float fd = pd - d0f, fh = ph - h0f, fw = pw - w0f;
                int d0 = (int)d0f, h0 = (int)h0f, w0 = (int)w0f;
                float wz0 = ((unsigned)d0       < 20u) ? (1.f - fd) : 0.f;
                float wz1 = ((unsigned)(d0 + 1) < 20u) ? fd         : 0.f;
                float wy0 = ((unsigned)h0       < 20u) ? (1.f - fh) : 0.f;
                float wy1 = ((unsigned)(h0 + 1) < 20u) ? fh         : 0.f;
                float wx0 = ((unsigned)w0       < 20u) ? (1.f - fw) : 0.f;
                float wx1 = ((unsigned)(w0 + 1) < 20u) ? fw         : 0.f;
                // independent clamps per corner (weights gate validity)
                int iz0 = min(max(d0, 0), 19),     iz1 = min(max(d0 + 1, 0), 19);
                int iy0 = min(max(h0, 0), 19),     iy1 = min(max(h0 + 1, 0), 19);
                int ix0 = min(max(w0, 0), 19),     ix1 = min(max(w0 + 1, 0), 19);
                int z0 = iz0 * 400, z1 = iz1 * 400;
                int y0 = iy0 * 20,  y1 = iy1 * 20;
                int r00 = z0 + y0, r01 = z0 + y1, r10 = z1 + y0, r11 = z1 + y1;
                float4 x000 = xt4[(r00 + ix0) * 8 + sub];
                float4 x001 = xt4[(r00 + ix1) * 8 + sub];
                float4 x010 = xt4[(r01 + ix0) * 8 + sub];
                float4 x011 = xt4[(r01 + ix1) * 8 + sub];
                float4 x100 = xt4[(r10 + ix0) * 8 + sub];
                float4 x101 = xt4[(r10 + ix1) * 8 + sub];
                float4 x110 = xt4[(r11 + ix0) * 8 + sub];
                float4 x111 = xt4[(r11 + ix1) * 8 + sub];
                float w00 = wz0 * wy0, w01 = wz0 * wy1, w10 = wz1 * wy0, w11 = wz1 * wy1;
                float w000 = w00 * wx0, w001 = w00 * wx1;
                float w010 = w01 * wx0, w011 = w01 * wx1;
                float w100 = w10 * wx0, w101 = w10 * wx1;
                float w110 = w11 * wx0, w111 = w11 * wx1;
                float4 s;
                s.x = w000*x000.x + w001*x001.x + w010*x010.x + w011*x011.x +
                      w100*x100.x + w101*x101.x + w110*x110.x + w111*x111.x;
                s.y = w000*x000.y + w001*x001.y + w010*x010.y + w011*x011.y +
                      w100*x100.y + w101*x101.y + w110*x110.y + w111*x111.y;
                s.z = w000*x000.z + w001*x001.z + w010*x010.z + w011*x011.z +
                      w100*x100.z + w101*x101.z + w110*x110.z + w111*x111.z;
                s.w = w000*x000.w + w001*x001.w + w010*x010.w + w011*x011.w +
                      w100*x100.w + w101*x101.w + w110*x110.w + w111*x111.w;
                float4 wt = wd4[t * 8 + sub];
                acc.x += wt.x * s.x;
                acc.y += wt.y * s.y;
                acc.z += wt.z * s.z;
                acc.w += wt.w * s.w;
            }
        }
    }
    float4 bias = ((const float4*)b_dw)[sub];
    acc.x += bias.x; acc.y += bias.y; acc.z += bias.z; acc.w += bias.w;
    ((float4*)g_attn1)[v * 8 + sub] = acc;
}

// ---------------------------------------------------------------------------
// Stage C: dilated (3) 7x7x7 depthwise conv, pad 9. Warp = 4 voxels,
// 8 lanes x 4 channels (float4).
// ---------------------------------------------------------------------------
__global__ __launch_bounds__(128) void spconv_kernel(const float* __restrict__ b_sp) {
    const int lane = threadIdx.x & 31;
    const int sub = lane & 7;
    const int qv = lane >> 3;
    const int v = blockIdx.x * 16 + (threadIdx.x >> 5) * 4 + qv;
    const int vz = v / 400;
    const int vy = (v / 20) % 20;
    const int vx = v % 20;
    const float4* __restrict__ a4 = (const float4*)g_attn1;
    const float4* __restrict__ w4 = (const float4*)g_wspt;

    float4 acc = ((const float4*)b_sp)[sub];
#pragma unroll 1
    for (int kz = 0; kz < 7; kz++) {
        int zi = vz + kz * 3 - 9;
        if ((unsigned)zi >= 20u) continue;
#pragma unroll 1
        for (int ky = 0; ky < 7; ky++) {
            int yi = vy + ky * 3 - 9;
            if ((unsigned)yi >= 20u) continue;
            int rowbase = (zi * 20 + yi) * 20;
            int tbase = (kz * 7 + ky) * 7;
#pragma unroll
            for (int kx = 0; kx < 7; kx++) {
                int xi = vx + kx * 3 - 9;
                if ((unsigned)xi < 20u) {
                    float4 wv = w4[(tbase + kx) * 8 + sub];
                    float4 av = a4[(rowbase + xi) * 8 + sub];
                    acc.x += wv.x * av.x;
                    acc.y += wv.y * av.y;
                    acc.z += wv.z * av.z;
                    acc.w += wv.w * av.w;
                }
            }
        }
    }
    ((float4*)g_attn2)[v * 8 + sub] = acc;
}

// ---------------------------------------------------------------------------
// Stage D: 32x32 pointwise (+bias) fused with final x*attn, NCDHW output.
// ---------------------------------------------------------------------------
__global__ __launch_bounds__(256) void pw_kernel(const float* __restrict__ w_pw,
                                                 const float* __restrict__ b_pw,
                                                 const float* __restrict__ x,
                                                 float* __restrict__ out) {
    __shared__ float a_s[32][33];
    __shared__ float w_s[1024];
    const int tid = threadIdx.x;
    const int v0 = blockIdx.x * 32;
#pragma unroll
    for (int i = 0; i < 4; i++) {
        int e = tid + 256 * i;
        w_s[e] = w_pw[e];
        int vv = e >> 5, cc = e & 31;
        a_s[vv][cc] = g_attn2[v0 * 32 + e];
    }
    __syncthreads();

    const int lane = tid & 31;
    const int wq = tid >> 5;
#pragma unroll
    for (int i = 0; i < 4; i++) {
        int o = wq + 8 * i;
        float acc = b_pw[o];
#pragma unroll
        for (int c = 0; c < 32; c++)
            acc += w_s[o * 32 + c] * a_s[lane][c];
        int v = v0 + lane;
        out[o * NV + v] = x[o * NV + v] * acc;
    }
}

// ---------------------------------------------------------------------------
extern "C" void kernel_launch(void* const* d_in, const int* in_sizes, int n_in,
                              void* d_out, int out_size) {
    const float* x     = (const float*)d_in[0];
    const float* w_off = (const float*)d_in[1];
    const float* b_off = (const float*)d_in[2];
    const float* w_dw  = (const float*)d_in[3];
    const float* b_dw  = (const float*)d_in[4];
    const float* w_sp  = (const float*)d_in[5];
    const float* b_sp  = (const float*)d_in[6];
    const float* w_pw  = (const float*)d_in[7];
    const float* b_pw  = (const float*)d_in[8];
    float* out = (float*)d_out;

    cudaFuncSetAttribute(gemm_off_kernel,
                         cudaFuncAttributeMaxDynamicSharedMemorySize, SMEM_SZ);

    prep_kernel<<<2000, 256>>>(x, w_dw, w_sp);
    prep_a_kernel<<<MPAD, 256>>>(w_off);               // 1 block per out-row
    dim3 gg(63, 2);                                    // 63 v-tiles x 2 n-tiles
    gemm_off_kernel<<<gg, 256, SMEM_SZ>>>(b_off);
    deform_kernel<<<500, 128>>>(b_dw);
    spconv_kernel<<<500, 128>>>(b_sp);
    pw_kernel<<<250, 256>>>(w_pw, b_pw, x, out);
}

// round 12
// speedup vs baseline: 2.8406x; 1.0375x over previous
#include <cuda_runtime.h>
#include <cuda_bf16.h>
#include <cstdint>

// Problem constants: B=1, C=32, S=20, K=5 (125 taps), offset conv out = 375 ch.
#define NV   8000     // 20^3 voxels
#define NC   32       // channels
#define MOUT 375      // 3*K3 offset channels
#define MPAD 384      // padded to 2 x 192 n-tiles

// Scratch (static device globals — no allocation APIs allowed)
__device__ __align__(16) float g_offv[NV * 384];   // offsets, [v][o] (padded)
__device__ __align__(16) float g_xt[NV * NC];      // x transposed to [v][c]
__device__ __align__(16) float g_attn1[NV * NC];   // deform output, [v][c]
__device__ __align__(16) float g_attn2[NV * NC];   // dilated depthwise output, [v][c]
__device__ __align__(16) float g_wdwt[125 * NC];   // w_dw transposed [t][c]
__device__ __align__(16) float g_wspt[343 * NC];   // w_sp transposed [t][c]
// bf16-split operands for the HMMA offset GEMM
__device__ __align__(16) __nv_bfloat16 g_A[125 * MPAD * 64];  // per tap: [m][hi c0..31 | lo c0..31]
__device__ __align__(16) __nv_bfloat16 g_xpair[NV * 64];      // per voxel: [hi c0..31 | lo c0..31]

__device__ __forceinline__ uint32_t smem_u32(const void* p) {
    uint32_t a;
    asm("{ .reg .u64 t; cvta.to.shared.u64 t, %1; cvt.u32.u64 %0, t; }" : "=r"(a) : "l"(p));
    return a;
}
__device__ __forceinline__ uint32_t sw128(uint32_t off) { return off ^ ((off >> 3) & 0x70); }

// cp.async 16B with zero-fill predication (src-size = 0 skips the read)
__device__ __forceinline__ void cp16(uint32_t dst, const void* src, bool pred) {
    int sz = pred ? 16 : 0;
    asm volatile("cp.async.cg.shared.global [%0], [%1], 16, %2;" :: "r"(dst), "l"(src), "r"(sz));
}
#define CP_COMMIT() asm volatile("cp.async.commit_group;" ::: "memory")
#define CP_WAIT(N)  asm volatile("cp.async.wait_group %0;" :: "n"(N) : "memory")

__device__ __forceinline__ void ldsm_x4(uint32_t& r0, uint32_t& r1, uint32_t& r2,
                                        uint32_t& r3, uint32_t addr) {
    asm volatile("ldmatrix.sync.aligned.m8n8.x4.shared.b16 {%0,%1,%2,%3}, [%4];"
                 : "=r"(r0), "=r"(r1), "=r"(r2), "=r"(r3) : "r"(addr));
}
__device__ __forceinline__ void mma16816(float* c, const uint32_t* a, const uint32_t* b) {
    asm volatile("mma.sync.aligned.m16n8k16.row.col.f32.bf16.bf16.f32 "
                 "{%0,%1,%2,%3}, {%4,%5,%6,%7}, {%8,%9}, {%0,%1,%2,%3};"
                 : "+f"(c[0]), "+f"(c[1]), "+f"(c[2]), "+f"(c[3])
                 : "r"(a[0]), "r"(a[1]), "r"(a[2]), "r"(a[3]), "r"(b[0]), "r"(b[1]));
}

// ---------------------------------------------------------------------------
// Prep: transposes + bf16 hi/lo split of x ([v][hi c|lo c])
// ---------------------------------------------------------------------------
__global__ __launch_bounds__(256) void prep_kernel(const float* __restrict__ x,
                                                   const float* __restrict__ w_dw,
                                                   const float* __restrict__ w_sp) {
    int idx = blockIdx.x * blockDim.x + threadIdx.x;
    if (idx < NV * 64) {  // g_xpair
        int v = idx >> 6, j = idx & 63, c = j & 31;
        float val = x[c * NV + v];
        __nv_bfloat16 hi = __float2bfloat16(val);
        g_xpair[idx] = (j < 32) ? hi : __float2bfloat16(val - __bfloat162float(hi));
    }
    if (idx < NV * NC) {
        int v = idx >> 5, c = idx & 31;
        g_xt[idx] = x[c * NV + v];
    }
    if (idx < 125 * NC) {
        int t = idx >> 5, c = idx & 31;
        g_wdwt[idx] = w_dw[c * 125 + t];
    }
    if (idx < 343 * NC) {
        int t = idx >> 5, c = idx & 31;
        g_wspt[idx] = w_sp[c * 343 + t];
    }
}

// Prep A (coalesced): one block per output row m.
__global__ __launch_bounds__(256) void prep_a_kernel(const float* __restrict__ w_off) {
    __shared__ float row[4000];
    const int m = blockIdx.x;
    const int tid = threadIdx.x;
    const bool mok = m < MOUT;
    if (mok)
        for (int i = tid; i < 4000; i += 256) row[i] = w_off[m * 4000 + i];
    __syncthreads();
    const int lane = tid & 31;
    const int wq = tid >> 5;
    for (int t = wq; t < 125; t += 8) {
        float wv = mok ? row[lane * 125 + t] : 0.f;
        __nv_bfloat16 hi = __float2bfloat16(wv);
        __nv_bfloat16 lo = __float2bfloat16(wv - __bfloat162float(hi));
        size_t base = ((size_t)t * MPAD + m) * 64;
        g_A[base + lane] = hi;
        g_A[base + 32 + lane] = lo;
    }
}

// ---------------------------------------------------------------------------
// Stage A: offset conv as 125 tap-GEMMs via mma.sync bf16. (unchanged)
// ---------------------------------------------------------------------------
#define WS0 0
#define WS1 24576
#define XS0 49152
#define XS1 65536
#define SMEM_SZ 81920

__global__ __launch_bounds__(256, 1) void gemm_off_kernel(const float* __restrict__ b_off) {
    extern __shared__ __align__(1024) char smem[];
    const uint32_t sb = smem_u32(smem);
    const int tid = threadIdx.x;
    const int lane = tid & 31;
    const int w = tid >> 5;
    const int wm = w & 1;          // m half (64 voxels)
    const int wn = w >> 1;         // n quarter (48 ch)
    const int v0 = blockIdx.x * 128;
    const int n0c = blockIdx.y * 192;

    const uint32_t wbase[2] = {sb + WS0, sb + WS1};
    const uint32_t xbase[2] = {sb + XS0, sb + XS1};

    const int bn = tid >> 1;             // row 0..127
    const int bh = (tid & 1) * 4;        // 16B-chunk base
    const int vq = v0 + bn;
    const bool vok = vq < NV;
    const int vz = vq / 400, vy = (vq / 20) % 20, vx = vq % 20;
    const char* __restrict__ xpB = (const char*)g_xpair;
    const char* __restrict__ gAB = (const char*)g_A;

    auto load_tap = [&](int t, int s) {
        const char* wsrc = gAB + (size_t)(t * MPAD + n0c) * 128;
#pragma unroll
        for (int i = 0; i < 6; i++) {
            int chunk = tid + (i << 8);
            int row = chunk >> 3, cb = (chunk & 7) << 4;
            cp16(wbase[s] + sw128((row << 7) + cb), wsrc + (row << 7) + cb, true);
        }
        const int dz = t / 25 - 2, dy = (t / 5) % 5 - 2, dx = t % 5 - 2;
        const bool valid = vok && ((unsigned)(vz + dz) < 20u) &&
                           ((unsigned)(vy + dy) < 20u) && ((unsigned)(vx + dx) < 20u);
        const int vsrc = valid ? (vq + dz * 400 + dy * 20 + dx) : 0;
        const char* xsrc = xpB + (size_t)vsrc * 128;
#pragma unroll
        for (int i = 0; i < 4; i++) {
            int cb = (bh + i) << 4;
            cp16(xbase[s] + sw128((bn << 7) + cb), xsrc + cb, valid);
        }
    };

    float acc[4][6][4];
#pragma unroll
    for (int mf = 0; mf < 4; mf++)
#pragma unroll
        for (int nf = 0; nf < 6; nf++)
#pragma unroll
            for (int q = 0; q < 4; q++) acc[mf][nf][q] = 0.f;

    const int x_row = wm * 64 + (lane & 15);
    const int x_hi16 = (lane >> 4) << 4;
    const int w_row4 = wn * 48 + ((lane >> 4) << 3) + (lane & 7);
    const int w_k16 = ((lane >> 3) & 1) << 4;

    auto loadA = [&](uint32_t (*f)[4], uint32_t xb, int xoff) {
#pragma unroll
        for (int mf = 0; mf < 4; mf++)
            ldsm_x4(f[mf][0], f[mf][1], f[mf][2], f[mf][3],
                    xb + sw128(((x_row + mf * 16) << 7) + xoff + x_hi16));
    };
    auto loadB = [&](uint32_t (*f)[2], uint32_t wb, int woff) {
#pragma unroll
        for (int p = 0; p < 3; p++) {
            uint32_t r0, r1, r2, r3;
            ldsm_x4(r0, r1, r2, r3,
                    wb + sw128(((w_row4 + p * 16) << 7) + woff + w_k16));
            f[2 * p][0] = r0;     f[2 * p][1] = r1;
            f[2 * p + 1][0] = r2; f[2 * p + 1][1] = r3;
        }
    };
    auto mmaSeg = [&](uint32_t (*a)[4], uint32_t (*b)[2]) {
#pragma unroll
        for (int mf = 0; mf < 4; mf++)
#pragma unroll
            for (int nf = 0; nf < 6; nf++)
                mma16816(acc[mf][nf], a[mf], b[nf]);
    };

    load_tap(0, 0);
    CP_COMMIT();

    for (int t = 0; t < 125; t++) {
        const int s = t & 1;
        if (t < 124) { load_tap(t + 1, s ^ 1); CP_COMMIT(); CP_WAIT(1); }
        else         { CP_WAIT(0); }
        __syncthreads();

        const uint32_t xb = xbase[s];
        const uint32_t wb = wbase[s];
        uint32_t Ah0[4][4], Ah1[4][4], Al[4][4], B[6][2];
        loadB(B, wb, 0);  loadA(Ah0, xb, 0);  mmaSeg(Ah0, B);
        loadA(Al, xb, 64);                     mmaSeg(Al, B);
        loadB(B, wb, 32); loadA(Ah1, xb, 32); mmaSeg(Ah1, B);
        loadA(Al, xb, 96);                     mmaSeg(Al, B);
        loadB(B, wb, 64);                      mmaSeg(Ah0, B);
        loadB(B, wb, 96);                      mmaSeg(Ah1, B);
        __syncthreads();
    }

    const int vr = v0 + wm * 64 + (lane >> 2);
    const int ob = n0c + wn * 48 + (lane & 3) * 2;
#pragma unroll
    for (int nf = 0; nf < 6; nf++) {
        int o = ob + nf * 8;
        float bias0 = (o < MOUT) ? b_off[o] : 0.f;
        float bias1 = (o + 1 < MOUT) ? b_off[o + 1] : 0.f;
#pragma unroll
        for (int mf = 0; mf < 4; mf++) {
            int v1 = vr + mf * 16, v2 = v1 + 8;
            if (v1 < NV) {
                float2 r = {acc[mf][nf][0] + bias0, acc[mf][nf][1] + bias1};
                *(float2*)&g_offv[(size_t)v1 * 384 + o] = r;
            }
            if (v2 < NV) {
                float2 r = {acc[mf][nf][2] + bias0, acc[mf][nf][3] + bias1};
                *(float2*)&g_offv[(size_t)v2 * 384 + o] = r;
            }
        }
    }
}

// ---------------------------------------------------------------------------
// Stage B: deformable depthwise conv. Warp = 2 voxels x 2 tap-halves;
// 8 lanes x 4 channels (float4). Half-warps split the 25 (kz,ky) rows
// (13 vs 12), combined via shfl_xor(16) butterfly at the end.
// ---------------------------------------------------------------------------
__global__ __launch_bounds__(128) void deform_kernel(const float* __restrict__ b_dw) {
    __shared__ __align__(16) float s_off[8 * 384];
    const int tid = threadIdx.x;
    const int lane = tid & 31;
    const int warp = tid >> 5;             // 0..3
    const int sub = lane & 7;              // channel-quad index
    const int qv = (lane >> 3) & 1;        // voxel within warp (0..1)
    const int th = lane >> 4;              // tap-half (0..1)
    const int vbase = blockIdx.x * 8;

    // stage this warp's 2 voxels of offsets (768 floats = 192 float4)
    {
        const float4* src = (const float4*)(g_offv + (size_t)(vbase + warp * 2) * 384);
        float4* dst = (float4*)(s_off + warp * 2 * 384);
#pragma unroll
        for (int i = 0; i < 6; i++) dst[lane + 32 * i] = src[lane + 32 * i];
    }
    __syncwarp();

    const int v = vbase + warp * 2 + qv;
    const int vz = v / 400;
    const int vy = (v / 20) % 20;
    const int vx = v % 20;
    const float* __restrict__ off = s_off + (warp * 2 + qv) * 384;
    const float4* __restrict__ xt4 = (const float4*)g_xt;
    const float4* __restrict__ wd4 = (const float4*)g_wdwt;

    float4 acc = {0.f, 0.f, 0.f, 0.f};
#pragma unroll 1
    for (int row = th; row < 25; row += 2) {
        const int kz = row / 5;
        const int ky = row - kz * 5;
        const float fz = (float)(vz + kz - 2);
        const float fy = (float)(vy + ky - 2);
        const int tb = row * 5;
#pragma unroll
        for (int kx = 0; kx < 5; kx++) {
            int t = tb + kx;
            float pd = fz + off[t * 3 + 0];
            float ph = fy + off[t * 3 + 1];
            float pw = (float)(vx + kx - 2) + off[t * 3 + 2];
            float d0f = floorf(pd), h0f = floorf(ph), w0f = floorf(pw);
            float fd = pd - d0f, fh = ph - h0f, fw = pw - w0f;
            int d0 = (int)d0f, h0 = (int)h0f, w0 = (int)w0f;
            float wz0 = ((unsigned)d0       < 20u) ? (1.f - fd) : 0.f;
            float wz1 = ((unsigned)(d0 + 1) < 20u) ? fd         : 0.f;
            float wy0 = ((unsigned)h0       < 20u) ? (1.f - fh) : 0.f;
            float wy1 = ((unsigned)(h0 + 1) < 20u) ? fh         : 0.f;
            float wx0 = ((unsigned)w0       < 20u) ? (1.f - fw) : 0.f;
            float wx1 = ((unsigned)(w0 + 1) < 20u) ? fw         : 0.f;
            // independent clamps per corner (weights gate validity)
            int iz0 = min(max(d0, 0), 19),     iz1 = min(max(d0 + 1, 0), 19);
            int iy0 = min(max(h0, 0), 19),     iy1 = min(max(h0 + 1, 0), 19);
            int ix0 = min(max(w0, 0), 19),     ix1 = min(max(w0 + 1, 0), 19);
            int z0 = iz0 * 400, z1 = iz1 * 400;
            int y0 = iy0 * 20,  y1 = iy1 * 20;
            int r00 = z0 + y0, r01 = z0 + y1, r10 = z1 + y0, r11 = z1 + y1;
            float4 x000 = xt4[(r00 + ix0) * 8 + sub];
            float4 x001 = xt4[(r00 + ix1) * 8 + sub];
            float4 x010 = xt4[(r01 + ix0) * 8 + sub];
            float4 x011 = xt4[(r01 + ix1) * 8 + sub];
            float4 x100 = xt4[(r10 + ix0) * 8 + sub];
            float4 x101 = xt4[(r10 + ix1) * 8 + sub];
            float4 x110 = xt4[(r11 + ix0) * 8 + sub];
            float4 x111 = xt4[(r11 + ix1) * 8 + sub];
            float w00 = wz0 * wy0, w01 = wz0 * wy1, w10 = wz1 * wy0, w11 = wz1 * wy1;
            float w000 = w00 * wx0, w001 = w00 * wx1;
            float w010 = w01 * wx0, w011 = w01 * wx1;
            float w100 = w10 * wx0, w101 = w10 * wx1;
            float w110 = w11 * wx0, w111 = w11 * wx1;
            float4 s;
            s.x = w000*x000.x + w001*x001.x + w010*x010.x + w011*x011.x +
                  w100*x100.x + w101*x101.x + w110*x110.x + w111*x111.x;
            s.y = w000*x000.y + w001*x001.y + w010*x010.y + w011*x011.y +
                  w100*x100.y + w101*x101.y + w110*x110.y + w111*x111.y;
            s.z = w000*x000.z + w001*x001.z + w010*x010.z + w011*x011.z +
                  w100*x100.z + w101*x101.z + w110*x110.z + w111*x111.z;
            s.w = w000*x000.w + w001*x001.w + w010*x010.w + w011*x011.w +
                  w100*x100.w + w101*x101.w + w110*x110.w + w111*x111.w;
            float4 wt = wd4[t * 8 + sub];
            acc.x += wt.x * s.x;
            acc.y += wt.y * s.y;
            acc.z += wt.z * s.z;
            acc.w += wt.w * s.w;
        }
    }
    // combine tap halves (lane i gets lane i^16's partial)
    acc.x += __shfl_xor_sync(0xffffffffu, acc.x, 16);
    acc.y += __shfl_xor_sync(0xffffffffu, acc.y, 16);
    acc.z += __shfl_xor_sync(0xffffffffu, acc.z, 16);
    acc.w += __shfl_xor_sync(0xffffffffu, acc.w, 16);
    if (th == 0) {
        float4 bias = ((const float4*)b_dw)[sub];
        acc.x += bias.x; acc.y += bias.y; acc.z += bias.z; acc.w += bias.w;
        ((float4*)g_attn1)[v * 8 + sub] = acc;
    }
}

// ---------------------------------------------------------------------------
// Stage C: dilated (3) 7x7x7 depthwise conv, pad 9. Warp = 2 voxels x
// 2 tap-halves; 8 lanes x 4 channels. Rows (kz,ky) 0..48 split odd/even.
// ---------------------------------------------------------------------------
__global__ __launch_bounds__(128) void spconv_kernel(const float* __restrict__ b_sp) {
    const int lane = threadIdx.x & 31;
    const int sub = lane & 7;
    const int qv = (lane >> 3) & 1;
    const int th = lane >> 4;
    const int v = blockIdx.x * 8 + (threadIdx.x >> 5) * 2 + qv;
    const int vz = v / 400;
    const int vy = (v / 20) % 20;
    const int vx = v % 20;
    const float4* __restrict__ a4 = (const float4*)g_attn1;
    const float4* __restrict__ w4 = (const float4*)g_wspt;

    float4 acc = {0.f, 0.f, 0.f, 0.f};
#pragma unroll 1
    for (int row = th; row < 49; row += 2) {
        const int kz = row / 7;
        const int ky = row - kz * 7;
        int zi = vz + kz * 3 - 9;
        if ((unsigned)zi >= 20u) continue;
        int yi = vy + ky * 3 - 9;
        if ((unsigned)yi >= 20u) continue;
        int rowbase = (zi * 20 + yi) * 20;
        int tbase = row * 7;
#pragma unroll
        for (int kx = 0; kx < 7; kx++) {
            int xi = vx + kx * 3 - 9;
            if ((unsigned)xi < 20u) {
                float4 wv = w4[(tbase + kx) * 8 + sub];
                float4 av = a4[(rowbase + xi) * 8 + sub];
                acc.x += wv.x * av.x;
                acc.y += wv.y * av.y;
                acc.z += wv.z * av.z;
                acc.w += wv.w * av.w;
            }
        }
    }
    acc.x += __shfl_xor_sync(0xffffffffu, acc.x, 16);
    acc.y += __shfl_xor_sync(0xffffffffu, acc.y, 16);
    acc.z += __shfl_xor_sync(0xffffffffu, acc.z, 16);
    acc.w += __shfl_xor_sync(0xffffffffu, acc.w, 16);
    if (th == 0) {
        float4 bias = ((const float4*)b_sp)[sub];
        acc.x += bias.x; acc.y += bias.y; acc.z += bias.z; acc.w += bias.w;
        ((float4*)g_attn2)[v * 8 + sub] = acc;
    }
}

// ---------------------------------------------------------------------------
// Stage D: 32x32 pointwise (+bias) fused with final x*attn, NCDHW output.
// ---------------------------------------------------------------------------
__global__ __launch_bounds__(256) void pw_kernel(const float* __restrict__ w_pw,
                                                 const float* __restrict__ b_pw,
                                                 const float* __restrict__ x,
                                                 float* __restrict__ out) {
    __shared__ float a_s[32][33];
    __shared__ float w_s[1024];
    const int tid = threadIdx.x;
    const int v0 = blockIdx.x * 32;
#pragma unroll
    for (int i = 0; i < 4; i++) {
        int e = tid + 256 * i;
        w_s[e] = w_pw[e];
        int vv = e >> 5, cc = e & 31;
        a_s[vv][cc] = g_attn2[v0 * 32 + e];
    }
    __syncthreads();

    const int lane = tid & 31;
    const int wq = tid >> 5;
#pragma unroll
    for (int i = 0; i < 4; i++) {
        int o = wq + 8 * i;
        float acc = b_pw[o];
#pragma unroll
        for (int c = 0; c < 32; c++)
            acc += w_s[o * 32 + c] * a_s[lane][c];
        int v = v0 + lane;
        out[o * NV + v] = x[o * NV + v] * acc;
    }
}

// ---------------------------------------------------------------------------
extern "C" void kernel_launch(void* const* d_in, const int* in_sizes, int n_in,
                              void* d_out, int out_size) {
    const float* x     = (const float*)d_in[0];
    const float* w_off = (const float*)d_in[1];
    const float* b_off = (const float*)d_in[2];
    const float* w_dw  = (const float*)d_in[3];
    const float* b_dw  = (const float*)d_in[4];
    const float* w_sp  = (const float*)d_in[5];
    const float* b_sp  = (const float*)d_in[6];
    const float* w_pw  = (const float*)d_in[7];
    const float* b_pw  = (const float*)d_in[8];
    float* out = (float*)d_out;

    cudaFuncSetAttribute(gemm_off_kernel,
                         cudaFuncAttributeMaxDynamicSharedMemorySize, SMEM_SZ);

    prep_kernel<<<2000, 256>>>(x, w_dw, w_sp);
    prep_a_kernel<<<MPAD, 256>>>(w_off);               // 1 block per out-row
    dim3 gg(63, 2);                                    // 63 v-tiles x 2 n-tiles
    gemm_off_kernel<<<gg, 256, SMEM_SZ>>>(b_off);
    deform_kernel<<<1000, 128>>>(b_dw);
    spconv_kernel<<<1000, 128>>>(b_sp);
    pw_kernel<<<250, 256>>>(w_pw, b_pw, x, out);
}

// round 13
// speedup vs baseline: 3.4123x; 1.2012x over previous
#include <cuda_runtime.h>
#include <cuda_fp16.h>
#include <cstdint>

// Problem constants: B=1, C=32, S=20, K=5 (125 taps), offset conv out = 375 ch.
#define NV   8000     // 20^3 voxels
#define NC   32       // channels
#define MOUT 375      // 3*K3 offset channels
#define MPAD 384      // padded to 2 x 192 n-tiles

// Scratch (static device globals — no allocation APIs allowed)
__device__ __align__(16) float g_offv[NV * 384];   // offsets, [v][o] (padded)
__device__ __align__(16) float g_xt[NV * NC];      // x transposed to [v][c]
__device__ __align__(16) float g_attn1[NV * NC];   // deform output, [v][c]
__device__ __align__(16) float g_attn2[NV * NC];   // dilated depthwise output, [v][c]
__device__ __align__(16) float g_wdwt[125 * NC];   // w_dw transposed [t][c]
__device__ __align__(16) float g_wspt[343 * NC];   // w_sp transposed [t][c]
// fp16-split operands for the HMMA offset GEMM
__device__ __align__(16) __half g_A[125 * MPAD * 64];   // per tap: [m][wh c0..31 | wl c0..31]
__device__ __align__(16) __half g_xpair[NV * 64];       // per voxel: [xh c0..31 | xl c0..31]

__device__ __forceinline__ uint32_t smem_u32(const void* p) {
    uint32_t a;
    asm("{ .reg .u64 t; cvta.to.shared.u64 t, %1; cvt.u32.u64 %0, t; }" : "=r"(a) : "l"(p));
    return a;
}
__device__ __forceinline__ uint32_t sw128(uint32_t off) { return off ^ ((off >> 3) & 0x70); }

// cp.async 16B with zero-fill predication (src-size = 0 skips the read)
__device__ __forceinline__ void cp16(uint32_t dst, const void* src, bool pred) {
    int sz = pred ? 16 : 0;
    asm volatile("cp.async.cg.shared.global [%0], [%1], 16, %2;" :: "r"(dst), "l"(src), "r"(sz));
}
#define CP_COMMIT() asm volatile("cp.async.commit_group;" ::: "memory")
#define CP_WAIT(N)  asm volatile("cp.async.wait_group %0;" :: "n"(N) : "memory")

__device__ __forceinline__ void ldsm_x4(uint32_t& r0, uint32_t& r1, uint32_t& r2,
                                        uint32_t& r3, uint32_t addr) {
    asm volatile("ldmatrix.sync.aligned.m8n8.x4.shared.b16 {%0,%1,%2,%3}, [%4];"
                 : "=r"(r0), "=r"(r1), "=r"(r2), "=r"(r3) : "r"(addr));
}
__device__ __forceinline__ void mma16816(float* c, const uint32_t* a, const uint32_t* b) {
    asm volatile("mma.sync.aligned.m16n8k16.row.col.f32.f16.f16.f32 "
                 "{%0,%1,%2,%3}, {%4,%5,%6,%7}, {%8,%9}, {%0,%1,%2,%3};"
                 : "+f"(c[0]), "+f"(c[1]), "+f"(c[2]), "+f"(c[3])
                 : "r"(a[0]), "r"(a[1]), "r"(a[2]), "r"(a[3]), "r"(b[0]), "r"(b[1]));
}

// ---------------------------------------------------------------------------
// Prep: transposes + fp16 hi/lo split of x ([v][xh c|xl c])
// ---------------------------------------------------------------------------
__global__ __launch_bounds__(256) void prep_kernel(const float* __restrict__ x,
                                                   const float* __restrict__ w_dw,
                                                   const float* __restrict__ w_sp) {
    int idx = blockIdx.x * blockDim.x + threadIdx.x;
    if (idx < NV * 64) {  // g_xpair
        int v = idx >> 6, j = idx & 63, c = j & 31;
        float val = x[c * NV + v];
        __half hi = __float2half(val);
        g_xpair[idx] = (j < 32) ? hi : __float2half(val - __half2float(hi));
    }
    if (idx < NV * NC) {
        int v = idx >> 5, c = idx & 31;
        g_xt[idx] = x[c * NV + v];
    }
    if (idx < 125 * NC) {
        int t = idx >> 5, c = idx & 31;
        g_wdwt[idx] = w_dw[c * 125 + t];
    }
    if (idx < 343 * NC) {
        int t = idx >> 5, c = idx & 31;
        g_wspt[idx] = w_sp[c * 343 + t];
    }
}

// Prep A (coalesced): one block per output row m. Only wh is consumed by the
// GEMM (2-product split); wl written for layout stability but never loaded.
__global__ __launch_bounds__(256) void prep_a_kernel(const float* __restrict__ w_off) {
    __shared__ float row[4000];
    const int m = blockIdx.x;
    const int tid = threadIdx.x;
    const bool mok = m < MOUT;
    if (mok)
        for (int i = tid; i < 4000; i += 256) row[i] = w_off[m * 4000 + i];
    __syncthreads();
    const int lane = tid & 31;
    const int wq = tid >> 5;
    for (int t = wq; t < 125; t += 8) {
        float wv = mok ? row[lane * 125 + t] : 0.f;
        __half hi = __float2half(wv);
        size_t base = ((size_t)t * MPAD + m) * 64;
        g_A[base + lane] = hi;
        g_A[base + 32 + lane] = __float2half(wv - __half2float(hi));
    }
}

// ---------------------------------------------------------------------------
// Stage A: offset conv as 125 tap-GEMMs via mma.sync fp16 (2-product split).
// CTA = 128 voxels x 192 out-ch, 8 warps (2m x 4n), warp tile 64v x 48o.
// Per tap 4 K16 segments: (xh0,wh0),(xl0,wh0),(xh1,wh1),(xl1,wh1).
// ---------------------------------------------------------------------------
#define WS0 0
#define WS1 24576
#define XS0 49152
#define XS1 65536
#define SMEM_SZ 81920

__global__ __launch_bounds__(256, 1) void gemm_off_kernel(const float* __restrict__ b_off) {
    extern __shared__ __align__(1024) char smem[];
    const uint32_t sb = smem_u32(smem);
    const int tid = threadIdx.x;
    const int lane = tid & 31;
    const int w = tid >> 5;
    const int wm = w & 1;          // m half (64 voxels)
    const int wn = w >> 1;         // n quarter (48 ch)
    const int v0 = blockIdx.x * 128;
    const int n0c = blockIdx.y * 192;

    const uint32_t wbase[2] = {sb + WS0, sb + WS1};
    const uint32_t xbase[2] = {sb + XS0, sb + XS1};

    const int bn = tid >> 1;             // row 0..127
    const int bh = (tid & 1) * 4;        // 16B-chunk base
    const int vq = v0 + bn;
    const bool vok = vq < NV;
    const int vz = vq / 400, vy = (vq / 20) % 20, vx = vq % 20;
    const char* __restrict__ xpB = (const char*)g_xpair;
    const char* __restrict__ gAB = (const char*)g_A;

    auto load_tap = [&](int t, int s) {
        // W tile: 192 rows, only first 64B (wh) of each 128B row
        const char* wsrc = gAB + (size_t)(t * MPAD + n0c) * 128;
#pragma unroll
        for (int i = 0; i < 3; i++) {
            int chunk = tid + (i << 8);            // 0..767
            int row = chunk >> 2, cb = (chunk & 3) << 4;
            cp16(wbase[s] + sw128((row << 7) + cb), wsrc + (row << 7) + cb, true);
        }
        // X tile: 128 rows x 128B (xh|xl) from g_xpair[shifted voxel]
        const int dz = t / 25 - 2, dy = (t / 5) % 5 - 2, dx = t % 5 - 2;
        const bool valid = vok && ((unsigned)(vz + dz) < 20u) &&
                           ((unsigned)(vy + dy) < 20u) && ((unsigned)(vx + dx) < 20u);
        const int vsrc = valid ? (vq + dz * 400 + dy * 20 + dx) : 0;
        const char* xsrc = xpB + (size_t)vsrc * 128;
#pragma unroll
        for (int i = 0; i < 4; i++) {
            int cb = (bh + i) << 4;
            cp16(xbase[s] + sw128((bn << 7) + cb), xsrc + cb, valid);
        }
    };

    float acc[4][6][4];
#pragma unroll
    for (int mf = 0; mf < 4; mf++)
#pragma unroll
        for (int nf = 0; nf < 6; nf++)
#pragma unroll
            for (int q = 0; q < 4; q++) acc[mf][nf][q] = 0.f;

    const int x_row = wm * 64 + (lane & 15);
    const int x_hi16 = (lane >> 4) << 4;
    const int w_row4 = wn * 48 + ((lane >> 4) << 3) + (lane & 7);
    const int w_k16 = ((lane >> 3) & 1) << 4;

    auto loadA = [&](uint32_t (*f)[4], uint32_t xb, int xoff) {
#pragma unroll
        for (int mf = 0; mf < 4; mf++)
            ldsm_x4(f[mf][0], f[mf][1], f[mf][2], f[mf][3],
                    xb + sw128(((x_row + mf * 16) << 7) + xoff + x_hi16));
    };
    auto loadB = [&](uint32_t (*f)[2], uint32_t wb, int woff) {
#pragma unroll
        for (int p = 0; p < 3; p++) {
            uint32_t r0, r1, r2, r3;
            ldsm_x4(r0, r1, r2, r3,
                    wb + sw128(((w_row4 + p * 16) << 7) + woff + w_k16));
            f[2 * p][0] = r0;     f[2 * p][1] = r1;
            f[2 * p + 1][0] = r2; f[2 * p + 1][1] = r3;
        }
    };
    auto mmaSeg = [&](uint32_t (*a)[4], uint32_t (*b)[2]) {
#pragma unroll
        for (int mf = 0; mf < 4; mf++)
#pragma unroll
            for (int nf = 0; nf < 6; nf++)
                mma16816(acc[mf][nf], a[mf], b[nf]);
    };

    load_tap(0, 0);
    CP_COMMIT();

    for (int t = 0; t < 125; t++) {
        const int s = t & 1;
        if (t < 124) { load_tap(t + 1, s ^ 1); CP_COMMIT(); CP_WAIT(1); }
        else         { CP_WAIT(0); }
        __syncthreads();

        const uint32_t xb = xbase[s];
        const uint32_t wb = wbase[s];
        uint32_t A[4][4], B[6][2];
        loadB(B, wb, 0);
        loadA(A, xb, 0);   mmaSeg(A, B);   // xh0 * wh0
        loadA(A, xb, 64);  mmaSeg(A, B);   // xl0 * wh0
        loadB(B, wb, 32);
        loadA(A, xb, 32);  mmaSeg(A, B);   // xh1 * wh1
        loadA(A, xb, 96);  mmaSeg(A, B);   // xl1 * wh1
        __syncthreads();
    }

    const int vr = v0 + wm * 64 + (lane >> 2);
    const int ob = n0c + wn * 48 + (lane & 3) * 2;
#pragma unroll
    for (int nf = 0; nf < 6; nf++) {
        int o = ob + nf * 8;
        float bias0 = (o < MOUT) ? b_off[o] : 0.f;
        float bias1 = (o + 1 < MOUT) ? b_off[o + 1] : 0.f;
#pragma unroll
        for (int mf = 0; mf < 4; mf++) {
            int v1 = vr + mf * 16, v2 = v1 + 8;
            if (v1 < NV) {
                float2 r = {acc[mf][nf][0] + bias0, acc[mf][nf][1] + bias1};
                *(float2*)&g_offv[(size_t)v1 * 384 + o] = r;
            }
            if (v2 < NV) {
                float2 r = {acc[mf][nf][2] + bias0, acc[mf][nf][3] + bias1};
                *(float2*)&g_offv[(size_t)v2 * 384 + o] = r;
            }
        }
    }
}

// ---------------------------------------------------------------------------
// Stage B: deformable depthwise conv. Warp = 1 voxel x 4 tap-quarters;
// 8 lanes x 4 channels (float4). Quarters split the 25 (kz,ky) rows
// (7/6/6/6), combined via shfl_xor(8)+shfl_xor(16) butterflies.
// ---------------------------------------------------------------------------
__global__ __launch_bounds__(128) void deform_kernel(const float* __restrict__ b_dw) {
    __shared__ __align__(16) float s_off[4 * 384];
    const int tid = threadIdx.x;
    const int lane = tid & 31;
    const int warp = tid >> 5;             // 0..3
    const int sub = lane & 7;              // channel-quad index
    const int tq = lane >> 3;              // tap-quarter (0..3)
    const int v = blockIdx.x * 4 + warp;

    // stage this warp's voxel offsets (384 floats = 96 float4)
    {
        const float4* src = (const float4*)(g_offv + (size_t)v * 384);
        float4* dst = (float4*)(s_off + warp * 384);
#pragma unroll
        for (int i = 0; i < 3; i++) dst[lane + 32 * i] = src[lane + 32 * i];
    }
    __syncwarp();

    const int vz = v / 400;
    const int vy = (v / 20) % 20;
    const int vx = v % 20;
    const float* __restrict__ off = s_off + warp * 384;
    const float4* __restrict__ xt4 = (const float4*)g_xt;
    const float4* __restrict__ wd4 = (const float4*)g_wdwt;

    float4 acc = {0.f, 0.f, 0.f, 0.f};
#pragma unroll 1
    for (int row = tq; row < 25; row += 4) {
        const int kz = row / 5;
        const int ky = row - kz * 5;
        const float fz = (float)(vz + kz - 2);
        const float fy = (float)(vy + ky - 2);
        const int tb = row * 5;
#pragma unroll
        for (int kx = 0; kx < 5; kx++) {
            int t = tb + kx;
            float pd = fz + off[t * 3 + 0];
            float ph = fy + off[t * 3 + 1];
            float pw = (float)(vx + kx - 2) + off[t * 3 + 2];
            float d0f = floorf(pd), h0f = floorf(ph), w0f = floorf(pw);
            float fd = pd - d0f, fh = ph - h0f, fw = pw - w0f;
            int d0 = (int)d0f, h0 = (int)h0f, w0 = (int)w0f;
            float wz0 = ((unsigned)d0       < 20u) ? (1.f - fd) : 0.f;
            float wz1 = ((unsigned)(d0 + 1) < 20u) ? fd         : 0.f;
            float wy0 = ((unsigned)h0       < 20u) ? (1.f - fh) : 0.f;
            float wy1 = ((unsigned)(h0 + 1) < 20u) ? fh         : 0.f;
            float wx0 = ((unsigned)w0       < 20u) ? (1.f - fw) : 0.f;
            float wx1 = ((unsigned)(w0 + 1) < 20u) ? fw         : 0.f;
            int iz0 = min(max(d0, 0), 19),     iz1 = min(max(d0 + 1, 0), 19);
            int iy0 = min(max(h0, 0), 19),     iy1 = min(max(h0 + 1, 0), 19);
            int ix0 = min(max(w0, 0), 19),     ix1 = min(max(w0 + 1, 0), 19);
            int z0 = iz0 * 400, z1 = iz1 * 400;
            int y0 = iy0 * 20,  y1 = iy1 * 20;
            int r00 = z0 + y0, r01 = z0 + y1, r10 = z1 + y0, r11 = z1 + y1;
            float4 x000 = xt4[(r00 + ix0) * 8 + sub];
            float4 x001 = xt4[(r00 + ix1) * 8 + sub];
            float4 x010 = xt4[(r01 + ix0) * 8 + sub];
            float4 x011 = xt4[(r01 + ix1) * 8 + sub];
            float4 x100 = xt4[(r10 + ix0) * 8 + sub];
            float4 x101 = xt4[(r10 + ix1) * 8 + sub];
            float4 x110 = xt4[(r11 + ix0) * 8 + sub];
            float4 x111 = xt4[(r11 + ix1) * 8 + sub];
            float w00 = wz0 * wy0, w01 = wz0 * wy1, w10 = wz1 * wy0, w11 = wz1 * wy1;
            float w000 = w00 * wx0, w001 = w00 * wx1;
            float w010 = w01 * wx0, w011 = w01 * wx1;
            float w100 = w10 * wx0, w101 = w10 * wx1;
            float w110 = w11 * wx0, w111 = w11 * wx1;
            float4 s;
            s.x = w000*x000.x + w001*x001.x + w010*x010.x + w011*x011.x +
                  w100*x100.x + w101*x101.x + w110*x110.x + w111*x111.x;
            s.y = w000*x000.y + w001*x001.y + w010*x010.y + w011*x011.y +
                  w100*x100.y + w101*x101.y + w110*x110.y + w111*x111.y;
            s.z = w000*x000.z + w001*x001.z + w010*x010.z + w011*x011.z +
                  w100*x100.z + w101*x101.z + w110*x110.z + w111*x111.z;
            s.w = w000*x000.w + w001*x001.w + w010*x010.w + w011*x011.w +
                  w100*x100.w + w101*x101.w + w110*x110.w + w111*x111.w;
            float4 wt = wd4[t * 8 + sub];
            acc.x += wt.x * s.x;
            acc.y += wt.y * s.y;
            acc.z += wt.z * s.z;
            acc.w += wt.w * s.w;
        }
    }
    // combine tap quarters
    acc.x += __shfl_xor_sync(0xffffffffu, acc.x, 8);
    acc.y += __shfl_xor_sync(0xffffffffu, acc.y, 8);
    acc.z += __shfl_xor_sync(0xffffffffu, acc.z, 8);
    acc.w += __shfl_xor_sync(0xffffffffu, acc.w, 8);
    acc.x += __shfl_xor_sync(0xffffffffu, acc.x, 16);
    acc.y += __shfl_xor_sync(0xffffffffu, acc.y, 16);
    acc.z += __shfl_xor_sync(0xffffffffu, acc.z, 16);
    acc.w += __shfl_xor_sync(0xffffffffu, acc.w, 16);
    if (tq == 0) {
        float4 bias = ((const float4*)b_dw)[sub];
        acc.x += bias.x; acc.y += bias.y; acc.z += bias.z; acc.w += bias.w;
        ((float4*)g_attn1)[v * 8 + sub] = acc;
    }
}

// ---------------------------------------------------------------------------
// Stage C: dilated (3) 7x7x7 depthwise conv, pad 9. Warp = 1 voxel x
// 4 tap-quarters; 8 lanes x 4 channels. 49 rows split 13/12/12/12.
// ---------------------------------------------------------------------------
__global__ __launch_bounds__(128) void spconv_kernel(const float* __restrict__ b_sp) {
    const int lane = threadIdx.x & 31;
    const int sub = lane & 7;
    const int tq = lane >> 3;
    const int v = blockIdx.x * 4 + (threadIdx.x >> 5);
    const int vz = v / 400;
    const int vy = (v / 20) % 20;
    const int vx = v % 20;
    const float4* __restrict__ a4 = (const float4*)g_attn1;
    const float4* __restrict__ w4 = (const float4*)g_wspt;

    float4 acc = {0.f, 0.f, 0.f, 0.f};
#pragma unroll 1
    for (int row = tq; row < 49; row += 4) {
        const int kz = row / 7;
        const int ky = row - kz * 7;
        int zi = vz + kz * 3 - 9;
        if ((unsigned)zi >= 20u) continue;
        int yi = vy + ky * 3 - 9;
        if ((unsigned)yi >= 20u) continue;
        int rowbase = (zi * 20 + yi) * 20;
        int tbase = row * 7;
#pragma unroll
        for (int kx = 0; kx < 7; kx++) {
            int xi = vx + kx * 3 - 9;
            if ((unsigned)xi < 20u) {
                float4 wv = w4[(tbase + kx) * 8 + sub];
                float4 av = a4[(rowbase + xi) * 8 + sub];
                acc.x += wv.x * av.x;
                acc.y += wv.y * av.y;
                acc.z += wv.z * av.z;
                acc.w += wv.w * av.w;
            }
        }
    }
    acc.x += __shfl_xor_sync(0xffffffffu, acc.x, 8);
    acc.y += __shfl_xor_sync(0xffffffffu, acc.y, 8);
    acc.z += __shfl_xor_sync(0xffffffffu, acc.z, 8);
    acc.w += __shfl_xor_sync(0xffffffffu, acc.w, 8);
    acc.x += __shfl_xor_sync(0xffffffffu, acc.x, 16);
    acc.y += __shfl_xor_sync(0xffffffffu, acc.y, 16);
    acc.z += __shfl_xor_sync(0xffffffffu, acc.z, 16);
    acc.w += __shfl_xor_sync(0xffffffffu, acc.w, 16);
    if (tq == 0) {
        float4 bias = ((const float4*)b_sp)[sub];
        acc.x += bias.x; acc.y += bias.y; acc.z += bias.z; acc.w += bias.w;
        ((float4*)g_attn2)[v * 8 + sub] = acc;
    }
}

// ---------------------------------------------------------------------------
// Stage D: 32x32 pointwise (+bias) fused with final x*attn, NCDHW output.
// ---------------------------------------------------------------------------
__global__ __launch_bounds__(256) void pw_kernel(const float* __restrict__ w_pw,
                                                 const float* __restrict__ b_pw,
                                                 const float* __restrict__ x,
                                                 float* __restrict__ out) {
    __shared__ float a_s[32][33];
    __shared__ float w_s[1024];
    const int tid = threadIdx.x;
    const int v0 = blockIdx.x * 32;
#pragma unroll
    for (int i = 0; i < 4; i++) {
        int e = tid + 256 * i;
        w_s[e] = w_pw[e];
        int vv = e >> 5, cc = e & 31;
        a_s[vv][cc] = g_attn2[v0 * 32 + e];
    }
    __syncthreads();

    const int lane = tid & 31;
    const int wq = tid >> 5;
#pragma unroll
    for (int i = 0; i < 4; i++) {
        int o = wq + 8 * i;
        float acc = b_pw[o];
#pragma unroll
        for (int c = 0; c < 32; c++)
            acc += w_s[o * 32 + c] * a_s[lane][c];
        int v = v0 + lane;
        out[o * NV + v] = x[o * NV + v] * acc;
    }
}

// ---------------------------------------------------------------------------
extern "C" void kernel_launch(void* const* d_in, const int* in_sizes, int n_in,
                              void* d_out, int out_size) {
    const float* x     = (const float*)d_in[0];
    const float* w_off = (const float*)d_in[1];
    const float* b_off = (const float*)d_in[2];
    const float* w_dw  = (const float*)d_in[3];
    const float* b_dw  = (const float*)d_in[4];
    const float* w_sp  = (const float*)d_in[5];
    const float* b_sp  = (const float*)d_in[6];
    const float* w_pw  = (const float*)d_in[7];
    const float* b_pw  = (const float*)d_in[8];
    float* out = (float*)d_out;

    cudaFuncSetAttribute(gemm_off_kernel,
                         cudaFuncAttributeMaxDynamicSharedMemorySize, SMEM_SZ);

    prep_kernel<<<2000, 256>>>(x, w_dw, w_sp);
    prep_a_kernel<<<MPAD, 256>>>(w_off);               // 1 block per out-row
    dim3 gg(63, 2);                                    // 63 v-tiles x 2 n-tiles
    gemm_off_kernel<<<gg, 256, SMEM_SZ>>>(b_off);
    deform_kernel<<<2000, 128>>>(b_dw);
    spconv_kernel<<<2000, 128>>>(b_sp);
    pw_kernel<<<250, 256>>>(w_pw, b_pw, x, out);
}

// round 14
// speedup vs baseline: 3.5210x; 1.0319x over previous
#include <cuda_runtime.h>
#include <cuda_fp16.h>
#include <cstdint>

// Problem constants: B=1, C=32, S=20, K=5 (125 taps), offset conv out = 375 ch.
#define NV   8000     // 20^3 voxels
#define NC   32       // channels
#define MOUT 375      // 3*K3 offset channels
#define MPAD 384      // padded to 2 x 192 n-tiles

// Scratch (static device globals — no allocation APIs allowed)
__device__ __align__(16) float g_offv[NV * 384];   // offsets, [v][o] (padded)
__device__ __align__(16) float g_xt[NV * NC];      // x transposed to [v][c]
__device__ __align__(16) float g_attn1[NV * NC];   // deform output, [v][c]
__device__ __align__(16) float g_attn2[NV * NC];   // dilated depthwise output, [v][c]
__device__ __align__(16) float g_wdwt[125 * NC];   // w_dw transposed [t][c]
__device__ __align__(16) float g_wspt[343 * NC];   // w_sp transposed [t][c]
// fp16-split operands for the HMMA offset GEMM
__device__ __align__(16) __half g_A[125 * MPAD * 64];   // per tap: [m][wh c0..31 | pad]
__device__ __align__(16) __half g_xpair[NV * 64];       // per voxel: [xh c0..31 | xl c0..31]

__device__ __forceinline__ uint32_t smem_u32(const void* p) {
    uint32_t a;
    asm("{ .reg .u64 t; cvta.to.shared.u64 t, %1; cvt.u32.u64 %0, t; }" : "=r"(a) : "l"(p));
    return a;
}
__device__ __forceinline__ uint32_t sw128(uint32_t off) { return off ^ ((off >> 3) & 0x70); }

// cp.async 16B with zero-fill predication (src-size = 0 skips the read)
__device__ __forceinline__ void cp16(uint32_t dst, const void* src, bool pred) {
    int sz = pred ? 16 : 0;
    asm volatile("cp.async.cg.shared.global [%0], [%1], 16, %2;" :: "r"(dst), "l"(src), "r"(sz));
}
#define CP_COMMIT() asm volatile("cp.async.commit_group;" ::: "memory")
#define CP_WAIT(N)  asm volatile("cp.async.wait_group %0;" :: "n"(N) : "memory")

__device__ __forceinline__ void ldsm_x4(uint32_t& r0, uint32_t& r1, uint32_t& r2,
                                        uint32_t& r3, uint32_t addr) {
    asm volatile("ldmatrix.sync.aligned.m8n8.x4.shared.b16 {%0,%1,%2,%3}, [%4];"
                 : "=r"(r0), "=r"(r1), "=r"(r2), "=r"(r3) : "r"(addr));
}
__device__ __forceinline__ void mma16816(float* c, const uint32_t* a, const uint32_t* b) {
    asm volatile("mma.sync.aligned.m16n8k16.row.col.f32.f16.f16.f32 "
                 "{%0,%1,%2,%3}, {%4,%5,%6,%7}, {%8,%9}, {%0,%1,%2,%3};"
                 : "+f"(c[0]), "+f"(c[1]), "+f"(c[2]), "+f"(c[3])
                 : "r"(a[0]), "r"(a[1]), "r"(a[2]), "r"(a[3]), "r"(b[0]), "r"(b[1]));
}

// ---------------------------------------------------------------------------
// Prep: transposes + fp16 hi/lo split of x ([v][xh c|xl c])
// ---------------------------------------------------------------------------
__global__ __launch_bounds__(256) void prep_kernel(const float* __restrict__ x,
                                                   const float* __restrict__ w_dw,
                                                   const float* __restrict__ w_sp) {
    int idx = blockIdx.x * blockDim.x + threadIdx.x;
    if (idx < NV * 64) {  // g_xpair
        int v = idx >> 6, j = idx & 63, c = j & 31;
        float val = x[c * NV + v];
        __half hi = __float2half(val);
        g_xpair[idx] = (j < 32) ? hi : __float2half(val - __half2float(hi));
    }
    if (idx < NV * NC) {
        int v = idx >> 5, c = idx & 31;
        g_xt[idx] = x[c * NV + v];
    }
    if (idx < 125 * NC) {
        int t = idx >> 5, c = idx & 31;
        g_wdwt[idx] = w_dw[c * 125 + t];
    }
    if (idx < 343 * NC) {
        int t = idx >> 5, c = idx & 31;
        g_wspt[idx] = w_sp[c * 343 + t];
    }
}

// Prep A (coalesced): one block per output row m. Only wh is stored (the
// 2-product GEMM never reads wl).
__global__ __launch_bounds__(256) void prep_a_kernel(const float* __restrict__ w_off) {
    __shared__ float row[4000];
    const int m = blockIdx.x;
    const int tid = threadIdx.x;
    const bool mok = m < MOUT;
    if (mok)
        for (int i = tid; i < 4000; i += 256) row[i] = w_off[m * 4000 + i];
    __syncthreads();
    const int lane = tid & 31;
    const int wq = tid >> 5;
    for (int t = wq; t < 125; t += 8) {
        float wv = mok ? row[lane * 125 + t] : 0.f;
        size_t base = ((size_t)t * MPAD + m) * 64;
        g_A[base + lane] = __float2half(wv);
    }
}

// ---------------------------------------------------------------------------
// Stage A: offset conv as 125 tap-GEMMs via mma.sync fp16 (2-product split).
// CTA = 128 voxels x 192 out-ch, 8 warps (2m x 4n), warp tile 64v x 48o.
// 3-stage cp.async pipeline, ONE __syncthreads per tap.
// ---------------------------------------------------------------------------
#define W_ST  24576
#define X_ST  16384
#define XS_BASE (3 * W_ST)                  // 73728
#define SMEM_SZ (XS_BASE + 3 * X_ST)        // 122880

__global__ __launch_bounds__(256, 1) void gemm_off_kernel(const float* __restrict__ b_off) {
    extern __shared__ __align__(1024) char smem[];
    const uint32_t sb = smem_u32(smem);
    const int tid = threadIdx.x;
    const int lane = tid & 31;
    const int w = tid >> 5;
    const int wm = w & 1;          // m half (64 voxels)
    const int wn = w >> 1;         // n quarter (48 ch)
    const int v0 = blockIdx.x * 128;
    const int n0c = blockIdx.y * 192;

    const int bn = tid >> 1;             // row 0..127
    const int bh = (tid & 1) * 4;        // 16B-chunk base
    const int vq = v0 + bn;
    const bool vok = vq < NV;
    const int vz = vq / 400, vy = (vq / 20) % 20, vx = vq % 20;
    const char* __restrict__ xpB = (const char*)g_xpair;
    const char* __restrict__ gAB = (const char*)g_A;

    auto load_tap = [&](int t, int s) {
        // W tile: 192 rows, first 64B (wh) of each 128B row slot
        const uint32_t wb = sb + s * W_ST;
        const char* wsrc = gAB + (size_t)(t * MPAD + n0c) * 128;
#pragma unroll
        for (int i = 0; i < 3; i++) {
            int chunk = tid + (i << 8);            // 0..767
            int row = chunk >> 2, cb = (chunk & 3) << 4;
            cp16(wb + sw128((row << 7) + cb), wsrc + (row << 7) + cb, true);
        }
        // X tile: 128 rows x 128B (xh|xl) from g_xpair[shifted voxel]
        const uint32_t xb = sb + XS_BASE + s * X_ST;
        const int dz = t / 25 - 2, dy = (t / 5) % 5 - 2, dx = t % 5 - 2;
        const bool valid = vok && ((unsigned)(vz + dz) < 20u) &&
                           ((unsigned)(vy + dy) < 20u) && ((unsigned)(vx + dx) < 20u);
        const int vsrc = valid ? (vq + dz * 400 + dy * 20 + dx) : 0;
        const char* xsrc = xpB + (size_t)vsrc * 128;
#pragma unroll
        for (int i = 0; i < 4; i++) {
            int cb = (bh + i) << 4;
            cp16(xb + sw128((bn << 7) + cb), xsrc + cb, valid);
        }
    };

    float acc[4][6][4];
#pragma unroll
    for (int mf = 0; mf < 4; mf++)
#pragma unroll
        for (int nf = 0; nf < 6; nf++)
#pragma unroll
            for (int q = 0; q < 4; q++) acc[mf][nf][q] = 0.f;

    const int x_row = wm * 64 + (lane & 15);
    const int x_hi16 = (lane >> 4) << 4;
    const int w_row4 = wn * 48 + ((lane >> 4) << 3) + (lane & 7);
    const int w_k16 = ((lane >> 3) & 1) << 4;

    auto loadA = [&](uint32_t (*f)[4], uint32_t xb, int xoff) {
#pragma unroll
        for (int mf = 0; mf < 4; mf++)
            ldsm_x4(f[mf][0], f[mf][1], f[mf][2], f[mf][3],
                    xb + sw128(((x_row + mf * 16) << 7) + xoff + x_hi16));
    };
    auto loadB = [&](uint32_t (*f)[2], uint32_t wb, int woff) {
#pragma unroll
        for (int p = 0; p < 3; p++) {
            uint32_t r0, r1, r2, r3;
            ldsm_x4(r0, r1, r2, r3,
                    wb + sw128(((w_row4 + p * 16) << 7) + woff + w_k16));
            f[2 * p][0] = r0;     f[2 * p][1] = r1;
            f[2 * p + 1][0] = r2; f[2 * p + 1][1] = r3;
        }
    };
    auto mmaSeg = [&](uint32_t (*a)[4], uint32_t (*b)[2]) {
#pragma unroll
        for (int mf = 0; mf < 4; mf++)
#pragma unroll
            for (int nf = 0; nf < 6; nf++)
                mma16816(acc[mf][nf], a[mf], b[nf]);
    };

    load_tap(0, 0); CP_COMMIT();
    load_tap(1, 1); CP_COMMIT();

    for (int t = 0; t < 125; t++) {
        const int s = t % 3;
        CP_WAIT(1);             // fill for stage s done (t+1's may be pending)
        __syncthreads();        // all warps done computing t-1 (stage (t-1)%3)
        if (t < 123) { load_tap(t + 2, (t + 2) % 3); CP_COMMIT(); }  // refills (t-1)%3

        const uint32_t xb = sb + XS_BASE + s * X_ST;
        const uint32_t wb = sb + s * W_ST;
        uint32_t A[4][4], B[6][2];
        loadB(B, wb, 0);
        loadA(A, xb, 0);   mmaSeg(A, B);   // xh0 * wh0
        loadA(A, xb, 64);  mmaSeg(A, B);   // xl0 * wh0
        loadB(B, wb, 32);
        loadA(A, xb, 32);  mmaSeg(A, B);   // xh1 * wh1
        loadA(A, xb, 96);  mmaSeg(A, B);   // xl1 * wh1
    }

    const int vr = v0 + wm * 64 + (lane >> 2);
    const int ob = n0c + wn * 48 + (lane & 3) * 2;
#pragma unroll
    for (int nf = 0; nf < 6; nf++) {
        int o = ob + nf * 8;
        float bias0 = (o < MOUT) ? b_off[o] : 0.f;
        float bias1 = (o + 1 < MOUT) ? b_off[o + 1] : 0.f;
#pragma unroll
        for (int mf = 0; mf < 4; mf++) {
            int v1 = vr + mf * 16, v2 = v1 + 8;
            if (v1 < NV) {
                float2 r = {acc[mf][nf][0] + bias0, acc[mf][nf][1] + bias1};
                *(float2*)&g_offv[(size_t)v1 * 384 + o] = r;
            }
            if (v2 < NV) {
                float2 r = {acc[mf][nf][2] + bias0, acc[mf][nf][3] + bias1};
                *(float2*)&g_offv[(size_t)v2 * 384 + o] = r;
            }
        }
    }
}

// ---------------------------------------------------------------------------
// Stage B: deformable depthwise conv. Warp = 2 voxels x 2 tap-halves;
// 8 lanes x 4 channels (float4). Half-warps split the 25 (kz,ky) rows
// (13 vs 12), combined via shfl_xor(16) butterfly at the end.
// ---------------------------------------------------------------------------
__global__ __launch_bounds__(128) void deform_kernel(const float* __restrict__ b_dw) {
    __shared__ __align__(16) float s_off[8 * 384];
    const int tid = threadIdx.x;
    const int lane = tid & 31;
    const int warp = tid >> 5;             // 0..3
    const int sub = lane & 7;              // channel-quad index
    const int qv = (lane >> 3) & 1;        // voxel within warp (0..1)
    const int th = lane >> 4;              // tap-half (0..1)
    const int vbase = blockIdx.x * 8;

    // stage this warp's 2 voxels of offsets (768 floats = 192 float4)
    {
        const float4* src = (const float4*)(g_offv + (size_t)(vbase + warp * 2) * 384);
        float4* dst = (float4*)(s_off + warp * 2 * 384);
#pragma unroll
        for (int i = 0; i < 6; i++) dst[lane + 32 * i] = src[lane + 32 * i];
    }
    __syncwarp();

    const int v = vbase + warp * 2 + qv;
    const int vz = v / 400;
    const int vy = (v / 20) % 20;
    const int vx = v % 20;
    const float* __restrict__ off = s_off + (warp * 2 + qv) * 384;
    const float4* __restrict__ xt4 = (const float4*)g_xt;
    const float4* __restrict__ wd4 = (const float4*)g_wdwt;

    float4 acc = {0.f, 0.f, 0.f, 0.f};
#pragma unroll 1
    for (int row = th; row < 25; row += 2) {
        const int kz = row / 5;
        const int ky = row - kz * 5;
        const float fz = (float)(vz + kz - 2);
        const float fy = (float)(vy + ky - 2);
        const int tb = row * 5;
#pragma unroll
        for (int kx = 0; kx < 5; kx++) {
            int t = tb + kx;
            float pd = fz + off[t * 3 + 0];
            float ph = fy + off[t * 3 + 1];
            float pw = (float)(vx + kx - 2) + off[t * 3 + 2];
            float d0f = floorf(pd), h0f = floorf(ph), w0f = floorf(pw);
            float fd = pd - d0f, fh = ph - h0f, fw = pw - w0f;
            int d0 = (int)d0f, h0 = (int)h0f, w0 = (int)w0f;
            float wz0 = ((unsigned)d0       < 20u) ? (1.f - fd) : 0.f;
            float wz1 = ((unsigned)(d0 + 1) < 20u) ? fd         : 0.f;
            float wy0 = ((unsigned)h0       < 20u) ? (1.f - fh) : 0.f;
            float wy1 = ((unsigned)(h0 + 1) < 20u) ? fh         : 0.f;
            float wx0 = ((unsigned)w0       < 20u) ? (1.f - fw) : 0.f;
            float wx1 = ((unsigned)(w0 + 1) < 20u) ? fw         : 0.f;
            int iz0 = min(max(d0, 0), 19),     iz1 = min(max(d0 + 1, 0), 19);
            int iy0 = min(max(h0, 0), 19),     iy1 = min(max(h0 + 1, 0), 19);
            int ix0 = min(max(w0, 0), 19),     ix1 = min(max(w0 + 1, 0), 19);
            int z0 = iz0 * 400, z1 = iz1 * 400;
            int y0 = iy0 * 20,  y1 = iy1 * 20;
            int r00 = z0 + y0, r01 = z0 + y1, r10 = z1 + y0, r11 = z1 + y1;
            float4 x000 = xt4[(r00 + ix0) * 8 + sub];
            float4 x001 = xt4[(r00 + ix1) * 8 + sub];
            float4 x010 = xt4[(r01 + ix0) * 8 + sub];
            float4 x011 = xt4[(r01 + ix1) * 8 + sub];
            float4 x100 = xt4[(r10 + ix0) * 8 + sub];
            float4 x101 = xt4[(r10 + ix1) * 8 + sub];
            float4 x110 = xt4[(r11 + ix0) * 8 + sub];
            float4 x111 = xt4[(r11 + ix1) * 8 + sub];
            float w00 = wz0 * wy0, w01 = wz0 * wy1, w10 = wz1 * wy0, w11 = wz1 * wy1;
            float w000 = w00 * wx0, w001 = w00 * wx1;
            float w010 = w01 * wx0, w011 = w01 * wx1;
            float w100 = w10 * wx0, w101 = w10 * wx1;
            float w110 = w11 * wx0, w111 = w11 * wx1;
            float4 s;
            s.x = w000*x000.x + w001*x001.x + w010*x010.x + w011*x011.x +
                  w100*x100.x + w101*x101.x + w110*x110.x + w111*x111.x;
            s.y = w000*x000.y + w001*x001.y + w010*x010.y + w011*x011.y +
                  w100*x100.y + w101*x101.y + w110*x110.y + w111*x111.y;
            s.z = w000*x000.z + w001*x001.z + w010*x010.z + w011*x011.z +
                  w100*x100.z + w101*x101.z + w110*x110.z + w111*x111.z;
            s.w = w000*x000.w + w001*x001.w + w010*x010.w + w011*x011.w +
                  w100*x100.w + w101*x101.w + w110*x110.w + w111*x111.w;
            float4 wt = wd4[t * 8 + sub];
            acc.x += wt.x * s.x;
            acc.y += wt.y * s.y;
            acc.z += wt.z * s.z;
            acc.w += wt.w * s.w;
        }
    }
    // combine tap halves (lane i gets lane i^16's partial)
    acc.x += __shfl_xor_sync(0xffffffffu, acc.x, 16);
    acc.y += __shfl_xor_sync(0xffffffffu, acc.y, 16);
    acc.z += __shfl_xor_sync(0xffffffffu, acc.z, 16);
    acc.w += __shfl_xor_sync(0xffffffffu, acc.w, 16);
    if (th == 0) {
        float4 bias = ((const float4*)b_dw)[sub];
        acc.x += bias.x; acc.y += bias.y; acc.z += bias.z; acc.w += bias.w;
        ((float4*)g_attn1)[v * 8 + sub] = acc;
    }
}

// ---------------------------------------------------------------------------
// Stage C: dilated (3) 7x7x7 depthwise conv, pad 9. Warp = 2 voxels x
// 2 tap-halves; 8 lanes x 4 channels. Rows (kz,ky) 0..48 split odd/even.
// ---------------------------------------------------------------------------
__global__ __launch_bounds__(128) void spconv_kernel(const float* __restrict__ b_sp) {
    const int lane = threadIdx.x & 31;
    const int sub = lane & 7;
    const int qv = (lane >> 3) & 1;
    const int th = lane >> 4;
    const int v = blockIdx.x * 8 + (threadIdx.x >> 5) * 2 + qv;
    const int vz = v / 400;
    const int vy = (v / 20) % 20;
    const int vx = v % 20;
    const float4* __restrict__ a4 = (const float4*)g_attn1;
    const float4* __restrict__ w4 = (const float4*)g_wspt;

    float4 acc = {0.f, 0.f, 0.f, 0.f};
#pragma unroll 1
    for (int row = th; row < 49; row += 2) {
        const int kz = row / 7;
        const int ky = row - kz * 7;
        int zi = vz + kz * 3 - 9;
        if ((unsigned)zi >= 20u) continue;
        int yi = vy + ky * 3 - 9;
        if ((unsigned)yi >= 20u) continue;
        int rowbase = (zi * 20 + yi) * 20;
        int tbase = row * 7;
#pragma unroll
        for (int kx = 0; kx < 7; kx++) {
            int xi = vx + kx * 3 - 9;
            if ((unsigned)xi < 20u) {
                float4 wv = w4[(tbase + kx) * 8 + sub];
                float4 av = a4[(rowbase + xi) * 8 + sub];
                acc.x += wv.x * av.x;
                acc.y += wv.y * av.y;
                acc.z += wv.z * av.z;
                acc.w += wv.w * av.w;
            }
        }
    }
    acc.x += __shfl_xor_sync(0xffffffffu, acc.x, 16);
    acc.y += __shfl_xor_sync(0xffffffffu, acc.y, 16);
    acc.z += __shfl_xor_sync(0xffffffffu, acc.z, 16);
    acc.w += __shfl_xor_sync(0xffffffffu, acc.w, 16);
    if (th == 0) {
        float4 bias = ((const float4*)b_sp)[sub];
        acc.x += bias.x; acc.y += bias.y; acc.z += bias.z; acc.w += bias.w;
        ((float4*)g_attn2)[v * 8 + sub] = acc;
    }
}

// ---------------------------------------------------------------------------
// Stage D: 32x32 pointwise (+bias) fused with final x*attn, NCDHW output.
// ---------------------------------------------------------------------------
__global__ __launch_bounds__(256) void pw_kernel(const float* __restrict__ w_pw,
                                                 const float* __restrict__ b_pw,
                                                 const float* __restrict__ x,
                                                 float* __restrict__ out) {
    __shared__ float a_s[32][33];
    __shared__ float w_s[1024];
    const int tid = threadIdx.x;
    const int v0 = blockIdx.x * 32;
#pragma unroll
    for (int i = 0; i < 4; i++) {
        int e = tid + 256 * i;
        w_s[e] = w_pw[e];
        int vv = e >> 5, cc = e & 31;
        a_s[vv][cc] = g_attn2[v0 * 32 + e];
    }
    __syncthreads();

    const int lane = tid & 31;
    const int wq = tid >> 5;
#pragma unroll
    for (int i = 0; i < 4; i++) {
        int o = wq + 8 * i;
        float acc = b_pw[o];
#pragma unroll
        for (int c = 0; c < 32; c++)
            acc += w_s[o * 32 + c] * a_s[lane][c];
        int v = v0 + lane;
        out[o * NV + v] = x[o * NV + v] * acc;
    }
}

// ---------------------------------------------------------------------------
extern "C" void kernel_launch(void* const* d_in, const int* in_sizes, int n_in,
                              void* d_out, int out_size) {
    const float* x     = (const float*)d_in[0];
    const float* w_off = (const float*)d_in[1];
    const float* b_off = (const float*)d_in[2];
    const float* w_dw  = (const float*)d_in[3];
    const float* b_dw  = (const float*)d_in[4];
    const float* w_sp  = (const float*)d_in[5];
    const float* b_sp  = (const float*)d_in[6];
    const float* w_pw  = (const float*)d_in[7];
    const float* b_pw  = (const float*)d_in[8];
    float* out = (float*)d_out;

    cudaFuncSetAttribute(gemm_off_kernel,
                         cudaFuncAttributeMaxDynamicSharedMemorySize, SMEM_SZ);

    prep_kernel<<<2000, 256>>>(x, w_dw, w_sp);
    prep_a_kernel<<<MPAD, 256>>>(w_off);               // 1 block per out-row
    dim3 gg(63, 2);                                    // 63 v-tiles x 2 n-tiles
    gemm_off_kernel<<<gg, 256, SMEM_SZ>>>(b_off);
    deform_kernel<<<1000, 128>>>(b_dw);
    spconv_kernel<<<1000, 128>>>(b_sp);
    pw_kernel<<<250, 256>>>(w_pw, b_pw, x, out);
}